// round 1
// baseline (speedup 1.0000x reference)
#include <cuda_runtime.h>
#include <math_constants.h>

#define N_NODES 50000
#define E_EDGES 800000
#define HEADS 4
#define CCH 64
#define IN_DIM 256
#define HC 256
#define NEG_SLOPE 0.2f

// ---------------- device scratch (no dynamic allocation allowed) ----------------
__device__ float g_h[N_NODES * HC];          // x @ W            51.2 MB
__device__ float g_asrc[N_NODES * HEADS];    // per-node att dot (src)
__device__ float g_adst[N_NODES * HEADS];    // per-node att dot (dst)
__device__ int   g_src[E_EDGES];
__device__ int   g_dst[E_EDGES];
__device__ int   g_deg[N_NODES];
__device__ int   g_rowstart[N_NODES + 1];
__device__ int   g_cursor[N_NODES];
__device__ int   g_csr[E_EDGES];             // src ids sorted by dst
__device__ int   g_is64;

// ---------------- dtype detection for edge_index (int64 vs int32) ----------------
__global__ void detect_kernel(const unsigned int* __restrict__ w) {
    __shared__ unsigned int r[256];
    unsigned int acc = 0;
    for (int i = threadIdx.x; i < 8192; i += 256) acc |= w[2 * i + 1];
    r[threadIdx.x] = acc;
    __syncthreads();
    if (threadIdx.x == 0) {
        unsigned int a = 0;
        #pragma unroll 8
        for (int i = 0; i < 256; i++) a |= r[i];
        g_is64 = (a == 0u) ? 1 : 0;   // all high words zero -> int64
    }
}

__global__ void convert_kernel(const void* __restrict__ ei) {
    int e = blockIdx.x * blockDim.x + threadIdx.x;
    if (e >= E_EDGES) return;
    int s, d;
    if (g_is64) {
        const long long* p = (const long long*)ei;
        s = (int)p[e];
        d = (int)p[E_EDGES + e];
    } else {
        const int* p = (const int*)ei;
        s = p[e];
        d = p[E_EDGES + e];
    }
    g_src[e] = s;
    g_dst[e] = d;
}

// ---------------- SGEMM: g_h = x[M,256] @ W[256,256] ----------------
#define BM 128
#define BN 128
#define BK 8
#define TM 8
#define TN 8
__global__ __launch_bounds__(256) void sgemm_kernel(const float* __restrict__ A,
                                                    const float* __restrict__ B) {
    __shared__ __align__(16) float As[BK][BM];
    __shared__ __align__(16) float Bs[BK][BN];

    const int tid  = threadIdx.x;
    const int row0 = blockIdx.y * BM;
    const int col0 = blockIdx.x * BN;

    const int tr = (tid / 16) * TM;
    const int tc = (tid % 16) * TN;

    // A tile loader: 128x8, float4 along K
    const int a_row = tid >> 1;
    const int a_col = (tid & 1) * 4;
    // B tile loader: 8x128, float4 along N
    const int b_row = tid >> 5;
    const int b_col = (tid & 31) * 4;

    float acc[TM][TN];
    #pragma unroll
    for (int i = 0; i < TM; i++)
        #pragma unroll
        for (int j = 0; j < TN; j++) acc[i][j] = 0.f;

    for (int k0 = 0; k0 < IN_DIM; k0 += BK) {
        int gr = row0 + a_row;
        float4 av = (gr < N_NODES) ? *(const float4*)&A[(size_t)gr * IN_DIM + k0 + a_col]
                                   : make_float4(0.f, 0.f, 0.f, 0.f);
        As[a_col + 0][a_row] = av.x;
        As[a_col + 1][a_row] = av.y;
        As[a_col + 2][a_row] = av.z;
        As[a_col + 3][a_row] = av.w;

        float4 bv = *(const float4*)&B[(size_t)(k0 + b_row) * HC + col0 + b_col];
        *(float4*)&Bs[b_row][b_col] = bv;
        __syncthreads();

        #pragma unroll
        for (int k = 0; k < BK; k++) {
            float ar[TM], br[TN];
            *(float4*)&ar[0] = *(const float4*)&As[k][tr];
            *(float4*)&ar[4] = *(const float4*)&As[k][tr + 4];
            *(float4*)&br[0] = *(const float4*)&Bs[k][tc];
            *(float4*)&br[4] = *(const float4*)&Bs[k][tc + 4];
            #pragma unroll
            for (int i = 0; i < TM; i++)
                #pragma unroll
                for (int j = 0; j < TN; j++) acc[i][j] += ar[i] * br[j];
        }
        __syncthreads();
    }

    #pragma unroll
    for (int i = 0; i < TM; i++) {
        int gr = row0 + tr + i;
        if (gr < N_NODES) {
            #pragma unroll
            for (int j = 0; j < TN; j += 4) {
                *(float4*)&g_h[(size_t)gr * HC + col0 + tc + j] =
                    make_float4(acc[i][j], acc[i][j + 1], acc[i][j + 2], acc[i][j + 3]);
            }
        }
    }
}

// ---------------- per-node attention dots: a_src[n,h], a_dst[n,h] ----------------
__global__ void attn_dot_kernel(const float* __restrict__ att_src,
                                const float* __restrict__ att_dst) {
    int warp = (blockIdx.x * blockDim.x + threadIdx.x) >> 5;
    int lane = threadIdx.x & 31;
    if (warp >= N_NODES) return;

    const float4* hrow = (const float4*)&g_h[(size_t)warp * HC];
    float4 v0 = hrow[lane * 2], v1 = hrow[lane * 2 + 1];
    float4 s0 = ((const float4*)att_src)[lane * 2];
    float4 s1 = ((const float4*)att_src)[lane * 2 + 1];
    float4 d0 = ((const float4*)att_dst)[lane * 2];
    float4 d1 = ((const float4*)att_dst)[lane * 2 + 1];

    float ss = v0.x * s0.x + v0.y * s0.y + v0.z * s0.z + v0.w * s0.w
             + v1.x * s1.x + v1.y * s1.y + v1.z * s1.z + v1.w * s1.w;
    float sd = v0.x * d0.x + v0.y * d0.y + v0.z * d0.z + v0.w * d0.w
             + v1.x * d1.x + v1.y * d1.y + v1.z * d1.z + v1.w * d1.w;

    // reduce within 8-lane groups (one head per group)
    #pragma unroll
    for (int off = 4; off >= 1; off >>= 1) {
        ss += __shfl_down_sync(0xffffffffu, ss, off, 8);
        sd += __shfl_down_sync(0xffffffffu, sd, off, 8);
    }
    if ((lane & 7) == 0) {
        int h = lane >> 3;
        g_asrc[warp * HEADS + h] = ss;
        g_adst[warp * HEADS + h] = sd;
    }
}

// ---------------- CSR build ----------------
__global__ void zero_deg_kernel() {
    int i = blockIdx.x * blockDim.x + threadIdx.x;
    if (i < N_NODES) g_deg[i] = 0;
}

__global__ void histo_kernel() {
    int e = blockIdx.x * blockDim.x + threadIdx.x;
    if (e < E_EDGES) atomicAdd(&g_deg[g_dst[e]], 1);
}

__global__ void scan_kernel() {
    __shared__ int tmp[1024];
    __shared__ int carry;
    if (threadIdx.x == 0) carry = 0;
    __syncthreads();
    for (int base = 0; base < N_NODES; base += 1024) {
        int i = base + threadIdx.x;
        int v = (i < N_NODES) ? g_deg[i] : 0;
        tmp[threadIdx.x] = v;
        __syncthreads();
        for (int off = 1; off < 1024; off <<= 1) {
            int add = (threadIdx.x >= off) ? tmp[threadIdx.x - off] : 0;
            __syncthreads();
            tmp[threadIdx.x] += add;
            __syncthreads();
        }
        int incl = tmp[threadIdx.x] + carry;
        if (i < N_NODES) {
            g_rowstart[i] = incl - v;
            g_cursor[i]   = incl - v;
        }
        __syncthreads();
        if (threadIdx.x == 1023) carry = incl;
        __syncthreads();
    }
    if (threadIdx.x == 0) g_rowstart[N_NODES] = carry;
}

__global__ void fill_kernel() {
    int e = blockIdx.x * blockDim.x + threadIdx.x;
    if (e < E_EDGES) {
        int d = g_dst[e];
        int slot = atomicAdd(&g_cursor[d], 1);
        g_csr[slot] = g_src[e];
    }
}

// ---------------- fused softmax + gather + bias + relu: one warp per dst node ----------------
__global__ __launch_bounds__(256) void gat_node_kernel(const float* __restrict__ bias,
                                                       float* __restrict__ out) {
    int warp = (blockIdx.x * blockDim.x + threadIdx.x) >> 5;
    int lane = threadIdx.x & 31;
    if (warp >= N_NODES) return;
    const int n  = warp;
    const int rs = g_rowstart[n];
    const int re = g_rowstart[n + 1];
    const int deg = re - rs;        // self edge at index == deg

    float4 ad4 = *(const float4*)&g_adst[n * HEADS];
    float ad[4] = {ad4.x, ad4.y, ad4.z, ad4.w};

    // ---- pass 1: segment max per head ----
    float m[4] = {-CUDART_INF_F, -CUDART_INF_F, -CUDART_INF_F, -CUDART_INF_F};
    for (int i = lane; i <= deg; i += 32) {
        int src = (i < deg) ? g_csr[rs + i] : n;
        float4 as4 = *(const float4*)&g_asrc[src * HEADS];
        float lg[4] = {as4.x + ad[0], as4.y + ad[1], as4.z + ad[2], as4.w + ad[3]};
        #pragma unroll
        for (int h = 0; h < 4; h++) {
            float v = lg[h] >= 0.f ? lg[h] : NEG_SLOPE * lg[h];
            m[h] = fmaxf(m[h], v);
        }
    }
    #pragma unroll
    for (int off = 16; off; off >>= 1)
        #pragma unroll
        for (int h = 0; h < 4; h++)
            m[h] = fmaxf(m[h], __shfl_xor_sync(0xffffffffu, m[h], off));

    // ---- pass 2: sum of exp per head ----
    float s[4] = {0.f, 0.f, 0.f, 0.f};
    for (int i = lane; i <= deg; i += 32) {
        int src = (i < deg) ? g_csr[rs + i] : n;
        float4 as4 = *(const float4*)&g_asrc[src * HEADS];
        float lg[4] = {as4.x + ad[0], as4.y + ad[1], as4.z + ad[2], as4.w + ad[3]};
        #pragma unroll
        for (int h = 0; h < 4; h++) {
            float v = lg[h] >= 0.f ? lg[h] : NEG_SLOPE * lg[h];
            s[h] += __expf(v - m[h]);
        }
    }
    #pragma unroll
    for (int off = 16; off; off >>= 1)
        #pragma unroll
        for (int h = 0; h < 4; h++)
            s[h] += __shfl_xor_sync(0xffffffffu, s[h], off);

    // ---- pass 3: weighted gather of features ----
    const int myh = lane >> 3;                  // lane covers cols [8*lane, 8*lane+8) -> head lane/8
    const float mh  = m[myh];
    const float inv = 1.f / (s[myh] + 1e-16f);
    const float adh = ad[myh];

    float acc[8] = {0.f, 0.f, 0.f, 0.f, 0.f, 0.f, 0.f, 0.f};
    for (int i = 0; i <= deg; i++) {
        int src = (i < deg) ? g_csr[rs + i] : n;
        float av = g_asrc[src * HEADS + myh];
        float lg = av + adh;
        lg = lg >= 0.f ? lg : NEG_SLOPE * lg;
        float alpha = __expf(lg - mh) * inv;
        const float4* hp = (const float4*)&g_h[(size_t)src * HC + lane * 8];
        float4 f0 = hp[0], f1 = hp[1];
        acc[0] += alpha * f0.x; acc[1] += alpha * f0.y;
        acc[2] += alpha * f0.z; acc[3] += alpha * f0.w;
        acc[4] += alpha * f1.x; acc[5] += alpha * f1.y;
        acc[6] += alpha * f1.z; acc[7] += alpha * f1.w;
    }

    float4 b0 = ((const float4*)bias)[lane * 2];
    float4 b1 = ((const float4*)bias)[lane * 2 + 1];
    float4 o0, o1;
    o0.x = fmaxf(acc[0] + b0.x, 0.f); o0.y = fmaxf(acc[1] + b0.y, 0.f);
    o0.z = fmaxf(acc[2] + b0.z, 0.f); o0.w = fmaxf(acc[3] + b0.w, 0.f);
    o1.x = fmaxf(acc[4] + b1.x, 0.f); o1.y = fmaxf(acc[5] + b1.y, 0.f);
    o1.z = fmaxf(acc[6] + b1.z, 0.f); o1.w = fmaxf(acc[7] + b1.w, 0.f);
    *(float4*)&out[(size_t)n * HC + lane * 8]     = o0;
    *(float4*)&out[(size_t)n * HC + lane * 8 + 4] = o1;
}

// ---------------- launch ----------------
extern "C" void kernel_launch(void* const* d_in, const int* in_sizes, int n_in,
                              void* d_out, int out_size) {
    const float* x       = (const float*)d_in[0];
    const void*  ei      = d_in[1];
    const float* W       = (const float*)d_in[2];
    const float* att_src = (const float*)d_in[3];
    const float* att_dst = (const float*)d_in[4];
    const float* bias    = (const float*)d_in[5];
    float*       out     = (float*)d_out;

    detect_kernel<<<1, 256>>>((const unsigned int*)ei);
    convert_kernel<<<(E_EDGES + 255) / 256, 256>>>(ei);

    dim3 gg(HC / BN, (N_NODES + BM - 1) / BM);
    sgemm_kernel<<<gg, 256>>>(x, W);

    attn_dot_kernel<<<(N_NODES + 7) / 8, 256>>>(att_src, att_dst);

    zero_deg_kernel<<<(N_NODES + 255) / 256, 256>>>();
    histo_kernel<<<(E_EDGES + 255) / 256, 256>>>();
    scan_kernel<<<1, 1024>>>();
    fill_kernel<<<(E_EDGES + 255) / 256, 256>>>();

    gat_node_kernel<<<(N_NODES + 7) / 8, 256>>>(bias, out);
}

// round 2
// speedup vs baseline: 1.6023x; 1.6023x over previous
#include <cuda_runtime.h>
#include <math_constants.h>
#include <cstdint>

#define N_NODES 50000
#define E_EDGES 800000
#define HEADS 4
#define IN_DIM 256
#define HC 256
#define NEG_SLOPE 0.2f

// ---------------- device scratch ----------------
__device__ float g_h[N_NODES * HC];          // x @ W   (51.2 MB)
__device__ float g_asrc[N_NODES * HEADS];
__device__ float g_adst[N_NODES * HEADS];
__device__ int   g_src[E_EDGES];
__device__ int   g_dst[E_EDGES];
__device__ int   g_deg[N_NODES];
__device__ int   g_rowstart[N_NODES + 1];
__device__ int   g_cursor[N_NODES];
__device__ int   g_csr[E_EDGES];
__device__ int   g_is64;

// ---------------- dtype detection ----------------
__global__ void detect_kernel(const unsigned int* __restrict__ w) {
    __shared__ unsigned int r[256];
    unsigned int acc = 0;
    for (int i = threadIdx.x; i < 8192; i += 256) acc |= w[2 * i + 1];
    r[threadIdx.x] = acc;
    __syncthreads();
    if (threadIdx.x == 0) {
        unsigned int a = 0;
        #pragma unroll 8
        for (int i = 0; i < 256; i++) a |= r[i];
        g_is64 = (a == 0u) ? 1 : 0;
    }
}

__global__ void zero_deg_kernel() {
    int i = blockIdx.x * blockDim.x + threadIdx.x;
    if (i < N_NODES) g_deg[i] = 0;
}

// convert + degree histogram fused
__global__ void convert_kernel(const void* __restrict__ ei) {
    int e = blockIdx.x * blockDim.x + threadIdx.x;
    if (e >= E_EDGES) return;
    int s, d;
    if (g_is64) {
        const long long* p = (const long long*)ei;
        s = (int)p[e];
        d = (int)p[E_EDGES + e];
    } else {
        const int* p = (const int*)ei;
        s = p[e];
        d = p[E_EDGES + e];
    }
    g_src[e] = s;
    g_dst[e] = d;
    atomicAdd(&g_deg[d], 1);
}

// ---------------- TF32 tensor-core GEMM + fused attention-dot epilogue ----------------
// h = x[50000,256] @ W[256,256]; also a_src[n,h], a_dst[n,h]
#define GBM 128
#define GBN 256
#define GBK 16
#define SA_STRIDE 136   // 136 % 32 == 8 -> conflict-free fragment LDS
#define SB_STRIDE 264   // 264 % 32 == 8
#define SA_FLOATS (GBK * SA_STRIDE)   // 2176
#define SB_FLOATS (GBK * SB_STRIDE)   // 4224
#define GEMM_SMEM_BYTES ((2 * SA_FLOATS + 2 * SB_FLOATS) * 4)  // 51200

__device__ __forceinline__ float to_tf32(float x) {
    unsigned int r;
    asm("cvt.rna.tf32.f32 %0, %1;" : "=r"(r) : "f"(x));
    return __uint_as_float(r);
}

__device__ __forceinline__ void mma_tf32(float4& d, const float* a, const float* b) {
    asm volatile(
        "mma.sync.aligned.m16n8k8.row.col.f32.tf32.tf32.f32 "
        "{%0,%1,%2,%3}, {%4,%5,%6,%7}, {%8,%9}, {%0,%1,%2,%3};\n"
        : "+f"(d.x), "+f"(d.y), "+f"(d.z), "+f"(d.w)
        : "r"(__float_as_uint(a[0])), "r"(__float_as_uint(a[1])),
          "r"(__float_as_uint(a[2])), "r"(__float_as_uint(a[3])),
          "r"(__float_as_uint(b[0])), "r"(__float_as_uint(b[1])));
}

__global__ __launch_bounds__(256, 1) void sgemm_tf32_kernel(
    const float* __restrict__ x, const float* __restrict__ W,
    const float* __restrict__ att_src, const float* __restrict__ att_dst) {
    extern __shared__ float smem[];
    float* AsBuf[2] = { smem, smem + SA_FLOATS };
    float* BsBuf[2] = { smem + 2 * SA_FLOATS, smem + 2 * SA_FLOATS + SB_FLOATS };

    const int tid  = threadIdx.x;
    const int w    = tid >> 5;
    const int lane = tid & 31;
    const int gid  = lane >> 2;   // groupID
    const int tig  = lane & 3;    // thread-in-group
    const int wm   = w & 1;       // row half   (64 rows)
    const int wn   = w >> 1;      // col group  (64 cols) == head index
    const int rowblk = blockIdx.x * GBM;

    float4 acc[4][8];
    #pragma unroll
    for (int i = 0; i < 4; i++)
        #pragma unroll
        for (int j = 0; j < 8; j++) acc[i][j] = make_float4(0.f, 0.f, 0.f, 0.f);

    float4 ar[2], br[4];

    // ---- loaders ----
    auto ldgA = [&](int k0) {
        #pragma unroll
        for (int j = 0; j < 2; j++) {
            int id  = tid + 256 * j;
            int row = id >> 2;
            int kc  = id & 3;
            int grow = rowblk + row;
            if (grow > N_NODES - 1) grow = N_NODES - 1;
            ar[j] = *(const float4*)&x[(size_t)grow * IN_DIM + k0 + kc * 4];
        }
    };
    auto ldgB = [&](int k0) {
        #pragma unroll
        for (int j = 0; j < 4; j++) {
            int id = tid + 256 * j;
            int kr = id >> 6;
            int c4 = id & 63;
            br[j] = *(const float4*)&W[(size_t)(k0 + kr) * HC + c4 * 4];
        }
    };
    auto stsA = [&](float* dst) {
        #pragma unroll
        for (int j = 0; j < 2; j++) {
            int id  = tid + 256 * j;
            int row = id >> 2;
            int kc  = id & 3;
            dst[(kc * 4 + 0) * SA_STRIDE + row] = to_tf32(ar[j].x);
            dst[(kc * 4 + 1) * SA_STRIDE + row] = to_tf32(ar[j].y);
            dst[(kc * 4 + 2) * SA_STRIDE + row] = to_tf32(ar[j].z);
            dst[(kc * 4 + 3) * SA_STRIDE + row] = to_tf32(ar[j].w);
        }
    };
    auto stsB = [&](float* dst) {
        #pragma unroll
        for (int j = 0; j < 4; j++) {
            int id = tid + 256 * j;
            int kr = id >> 6;
            int c4 = id & 63;
            float4 t = make_float4(to_tf32(br[j].x), to_tf32(br[j].y),
                                   to_tf32(br[j].z), to_tf32(br[j].w));
            *(float4*)&dst[kr * SB_STRIDE + c4 * 4] = t;
        }
    };

    // ---- prologue ----
    ldgA(0); ldgB(0);
    stsA(AsBuf[0]); stsB(BsBuf[0]);
    ldgA(GBK); ldgB(GBK);
    __syncthreads();

    const int NIT = IN_DIM / GBK;   // 16
    for (int it = 0; it < NIT; ++it) {
        const float* Ac = AsBuf[it & 1];
        const float* Bc = BsBuf[it & 1];
        #pragma unroll
        for (int ks = 0; ks < 2; ks++) {
            const int kb = ks * 8;
            float afr[4][4], bfr[8][2];
            #pragma unroll
            for (int mt = 0; mt < 4; mt++) {
                int mb = wm * 64 + mt * 16 + gid;
                afr[mt][0] = Ac[(kb + tig) * SA_STRIDE + mb];
                afr[mt][1] = Ac[(kb + tig) * SA_STRIDE + mb + 8];
                afr[mt][2] = Ac[(kb + tig + 4) * SA_STRIDE + mb];
                afr[mt][3] = Ac[(kb + tig + 4) * SA_STRIDE + mb + 8];
            }
            #pragma unroll
            for (int nt = 0; nt < 8; nt++) {
                int nb = wn * 64 + nt * 8 + gid;
                bfr[nt][0] = Bc[(kb + tig) * SB_STRIDE + nb];
                bfr[nt][1] = Bc[(kb + tig + 4) * SB_STRIDE + nb];
            }
            #pragma unroll
            for (int mt = 0; mt < 4; mt++)
                #pragma unroll
                for (int nt = 0; nt < 8; nt++)
                    mma_tf32(acc[mt][nt], afr[mt], bfr[nt]);
        }
        if (it + 1 < NIT) {
            __syncthreads();
            stsA(AsBuf[(it + 1) & 1]); stsB(BsBuf[(it + 1) & 1]);
            if (it + 2 < NIT) { ldgA((it + 2) * GBK); ldgB((it + 2) * GBK); }
            __syncthreads();
        }
    }

    // ---- epilogue: store h + fused per-node attention dots ----
    float2 avs[8], avd[8];
    #pragma unroll
    for (int nt = 0; nt < 8; nt++) {
        int c = wn * 64 + nt * 8 + tig * 2;
        avs[nt] = *(const float2*)&att_src[c];
        avd[nt] = *(const float2*)&att_dst[c];
    }

    #pragma unroll
    for (int mt = 0; mt < 4; mt++) {
        int row0 = rowblk + wm * 64 + mt * 16 + gid;
        int row1 = row0 + 8;
        float s0 = 0.f, s1 = 0.f, t0 = 0.f, t1 = 0.f;
        #pragma unroll
        for (int nt = 0; nt < 8; nt++) {
            float4 d = acc[mt][nt];
            int col = wn * 64 + nt * 8 + tig * 2;
            if (row0 < N_NODES) *(float2*)&g_h[(size_t)row0 * HC + col] = make_float2(d.x, d.y);
            if (row1 < N_NODES) *(float2*)&g_h[(size_t)row1 * HC + col] = make_float2(d.z, d.w);
            s0 += d.x * avs[nt].x + d.y * avs[nt].y;
            s1 += d.z * avs[nt].x + d.w * avs[nt].y;
            t0 += d.x * avd[nt].x + d.y * avd[nt].y;
            t1 += d.z * avd[nt].x + d.w * avd[nt].y;
        }
        #pragma unroll
        for (int off = 1; off <= 2; off <<= 1) {
            s0 += __shfl_xor_sync(0xffffffffu, s0, off);
            s1 += __shfl_xor_sync(0xffffffffu, s1, off);
            t0 += __shfl_xor_sync(0xffffffffu, t0, off);
            t1 += __shfl_xor_sync(0xffffffffu, t1, off);
        }
        if (tig == 0) {
            if (row0 < N_NODES) { g_asrc[row0 * HEADS + wn] = s0; g_adst[row0 * HEADS + wn] = t0; }
            if (row1 < N_NODES) { g_asrc[row1 * HEADS + wn] = s1; g_adst[row1 * HEADS + wn] = t1; }
        }
    }
}

// ---------------- scan (shuffle-based, single block) ----------------
__global__ void scan_kernel() {
    __shared__ int wsums[32];
    __shared__ int carry_s;
    const int tid = threadIdx.x, wid = tid >> 5, lane = tid & 31;
    if (tid == 0) carry_s = 0;
    __syncthreads();
    for (int base = 0; base < N_NODES; base += 1024) {
        int i = base + tid;
        int v = (i < N_NODES) ? g_deg[i] : 0;
        int incl = v;
        #pragma unroll
        for (int off = 1; off < 32; off <<= 1) {
            int t = __shfl_up_sync(0xffffffffu, incl, off);
            if (lane >= off) incl += t;
        }
        if (lane == 31) wsums[wid] = incl;
        __syncthreads();
        if (wid == 0) {
            int wv = wsums[lane];
            #pragma unroll
            for (int off = 1; off < 32; off <<= 1) {
                int t = __shfl_up_sync(0xffffffffu, wv, off);
                if (lane >= off) wv += t;
            }
            wsums[lane] = wv;
        }
        __syncthreads();
        int woff = ((wid > 0) ? wsums[wid - 1] : 0) + carry_s;
        if (i < N_NODES) {
            int start = woff + incl - v;
            g_rowstart[i] = start;
            g_cursor[i]   = start;
        }
        __syncthreads();
        if (tid == 0) carry_s += wsums[31];
        __syncthreads();
    }
    if (tid == 0) g_rowstart[N_NODES] = carry_s;
}

__global__ void fill_kernel() {
    int e = blockIdx.x * blockDim.x + threadIdx.x;
    if (e < E_EDGES) {
        int d = g_dst[e];
        int slot = atomicAdd(&g_cursor[d], 1);
        g_csr[slot] = g_src[e];
    }
}

// ---------------- fused softmax + gather + bias + relu ----------------
#define CAP 96
__global__ __launch_bounds__(256) void gat_node_kernel(const float* __restrict__ bias,
                                                       float* __restrict__ out) {
    __shared__ float s_lg[8][CAP][4];
    __shared__ int   s_src[8][CAP];

    const int w    = threadIdx.x >> 5;
    const int lane = threadIdx.x & 31;
    const int node = (blockIdx.x * blockDim.x + threadIdx.x) >> 5;
    if (node >= N_NODES) return;
    const int n   = node;
    const int rs  = g_rowstart[n];
    const int deg = g_rowstart[n + 1] - rs;
    const int tot = deg + 1;   // + self loop

    float4 ad4 = *(const float4*)&g_adst[n * HEADS];
    float ad[4] = {ad4.x, ad4.y, ad4.z, ad4.w};
    const int myh = lane >> 3;

    float acc[8] = {0.f, 0.f, 0.f, 0.f, 0.f, 0.f, 0.f, 0.f};

    if (tot <= CAP) {
        // ---- pass 1: logits -> smem, max ----
        float m[4] = {-CUDART_INF_F, -CUDART_INF_F, -CUDART_INF_F, -CUDART_INF_F};
        for (int i = lane; i < tot; i += 32) {
            int src = (i < deg) ? g_csr[rs + i] : n;
            s_src[w][i] = src;
            float4 a4 = *(const float4*)&g_asrc[src * HEADS];
            float lg[4] = {a4.x + ad[0], a4.y + ad[1], a4.z + ad[2], a4.w + ad[3]};
            #pragma unroll
            for (int h = 0; h < 4; h++) {
                lg[h] = lg[h] >= 0.f ? lg[h] : NEG_SLOPE * lg[h];
                m[h] = fmaxf(m[h], lg[h]);
            }
            *(float4*)&s_lg[w][i][0] = make_float4(lg[0], lg[1], lg[2], lg[3]);
        }
        #pragma unroll
        for (int off = 16; off; off >>= 1)
            #pragma unroll
            for (int h = 0; h < 4; h++)
                m[h] = fmaxf(m[h], __shfl_xor_sync(0xffffffffu, m[h], off));

        // ---- pass 2: exp in-place, sum ----
        float s[4] = {0.f, 0.f, 0.f, 0.f};
        for (int i = lane; i < tot; i += 32) {
            float4 L = *(const float4*)&s_lg[w][i][0];
            float e0 = __expf(L.x - m[0]);
            float e1 = __expf(L.y - m[1]);
            float e2 = __expf(L.z - m[2]);
            float e3 = __expf(L.w - m[3]);
            s[0] += e0; s[1] += e1; s[2] += e2; s[3] += e3;
            *(float4*)&s_lg[w][i][0] = make_float4(e0, e1, e2, e3);
        }
        #pragma unroll
        for (int off = 16; off; off >>= 1)
            #pragma unroll
            for (int h = 0; h < 4; h++)
                s[h] += __shfl_xor_sync(0xffffffffu, s[h], off);

        const float inv = 1.f / (s[myh] + 1e-16f);
        __syncwarp();

        // ---- pass 3: weighted feature gather (unroll x2) ----
        for (int i = 0; i < tot; i += 2) {
            int  src0 = s_src[w][i];
            float al0 = s_lg[w][i][myh] * inv;
            bool has1 = (i + 1 < tot);
            int  src1 = has1 ? s_src[w][i + 1] : src0;
            float al1 = has1 ? s_lg[w][i + 1][myh] * inv : 0.f;

            const float4* p0 = (const float4*)&g_h[(size_t)src0 * HC + lane * 8];
            const float4* p1 = (const float4*)&g_h[(size_t)src1 * HC + lane * 8];
            float4 f00 = p0[0], f01 = p0[1];
            float4 f10 = p1[0], f11 = p1[1];
            acc[0] += al0 * f00.x + al1 * f10.x;
            acc[1] += al0 * f00.y + al1 * f10.y;
            acc[2] += al0 * f00.z + al1 * f10.z;
            acc[3] += al0 * f00.w + al1 * f10.w;
            acc[4] += al0 * f01.x + al1 * f11.x;
            acc[5] += al0 * f01.y + al1 * f11.y;
            acc[6] += al0 * f01.z + al1 * f11.z;
            acc[7] += al0 * f01.w + al1 * f11.w;
        }
    } else {
        // ---- fallback: 3 global passes (degenerate high-degree nodes) ----
        float m[4] = {-CUDART_INF_F, -CUDART_INF_F, -CUDART_INF_F, -CUDART_INF_F};
        for (int i = lane; i < tot; i += 32) {
            int src = (i < deg) ? g_csr[rs + i] : n;
            float4 a4 = *(const float4*)&g_asrc[src * HEADS];
            float lg[4] = {a4.x + ad[0], a4.y + ad[1], a4.z + ad[2], a4.w + ad[3]};
            #pragma unroll
            for (int h = 0; h < 4; h++) {
                float v = lg[h] >= 0.f ? lg[h] : NEG_SLOPE * lg[h];
                m[h] = fmaxf(m[h], v);
            }
        }
        #pragma unroll
        for (int off = 16; off; off >>= 1)
            #pragma unroll
            for (int h = 0; h < 4; h++)
                m[h] = fmaxf(m[h], __shfl_xor_sync(0xffffffffu, m[h], off));

        float s[4] = {0.f, 0.f, 0.f, 0.f};
        for (int i = lane; i < tot; i += 32) {
            int src = (i < deg) ? g_csr[rs + i] : n;
            float4 a4 = *(const float4*)&g_asrc[src * HEADS];
            float lg[4] = {a4.x + ad[0], a4.y + ad[1], a4.z + ad[2], a4.w + ad[3]};
            #pragma unroll
            for (int h = 0; h < 4; h++) {
                float v = lg[h] >= 0.f ? lg[h] : NEG_SLOPE * lg[h];
                s[h] += __expf(v - m[h]);
            }
        }
        #pragma unroll
        for (int off = 16; off; off >>= 1)
            #pragma unroll
            for (int h = 0; h < 4; h++)
                s[h] += __shfl_xor_sync(0xffffffffu, s[h], off);

        const float mh  = m[myh];
        const float inv = 1.f / (s[myh] + 1e-16f);
        const float adh = ad[myh];
        for (int i = 0; i < tot; i++) {
            int src = (i < deg) ? g_csr[rs + i] : n;
            float av = g_asrc[src * HEADS + myh];
            float lg = av + adh;
            lg = lg >= 0.f ? lg : NEG_SLOPE * lg;
            float alpha = __expf(lg - mh) * inv;
            const float4* hp = (const float4*)&g_h[(size_t)src * HC + lane * 8];
            float4 f0 = hp[0], f1 = hp[1];
            acc[0] += alpha * f0.x; acc[1] += alpha * f0.y;
            acc[2] += alpha * f0.z; acc[3] += alpha * f0.w;
            acc[4] += alpha * f1.x; acc[5] += alpha * f1.y;
            acc[6] += alpha * f1.z; acc[7] += alpha * f1.w;
        }
    }

    float4 b0 = ((const float4*)bias)[lane * 2];
    float4 b1 = ((const float4*)bias)[lane * 2 + 1];
    float4 o0, o1;
    o0.x = fmaxf(acc[0] + b0.x, 0.f); o0.y = fmaxf(acc[1] + b0.y, 0.f);
    o0.z = fmaxf(acc[2] + b0.z, 0.f); o0.w = fmaxf(acc[3] + b0.w, 0.f);
    o1.x = fmaxf(acc[4] + b1.x, 0.f); o1.y = fmaxf(acc[5] + b1.y, 0.f);
    o1.z = fmaxf(acc[6] + b1.z, 0.f); o1.w = fmaxf(acc[7] + b1.w, 0.f);
    *(float4*)&out[(size_t)n * HC + lane * 8]     = o0;
    *(float4*)&out[(size_t)n * HC + lane * 8 + 4] = o1;
}

// ---------------- launch ----------------
extern "C" void kernel_launch(void* const* d_in, const int* in_sizes, int n_in,
                              void* d_out, int out_size) {
    const float* x       = (const float*)d_in[0];
    const void*  ei      = d_in[1];
    const float* W       = (const float*)d_in[2];
    const float* att_src = (const float*)d_in[3];
    const float* att_dst = (const float*)d_in[4];
    const float* bias    = (const float*)d_in[5];
    float*       out     = (float*)d_out;

    cudaFuncSetAttribute(sgemm_tf32_kernel,
                         cudaFuncAttributeMaxDynamicSharedMemorySize, GEMM_SMEM_BYTES);

    detect_kernel<<<1, 256>>>((const unsigned int*)ei);
    zero_deg_kernel<<<(N_NODES + 255) / 256, 256>>>();
    convert_kernel<<<(E_EDGES + 255) / 256, 256>>>(ei);

    int gemm_blocks = (N_NODES + GBM - 1) / GBM;   // 391
    sgemm_tf32_kernel<<<gemm_blocks, 256, GEMM_SMEM_BYTES>>>(x, W, att_src, att_dst);

    scan_kernel<<<1, 1024>>>();
    fill_kernel<<<(E_EDGES + 255) / 256, 256>>>();

    gat_node_kernel<<<(N_NODES + 7) / 8, 256>>>(bias, out);
}

// round 3
// speedup vs baseline: 1.8450x; 1.1515x over previous
#include <cuda_runtime.h>
#include <math_constants.h>
#include <cstdint>

#define N_NODES 50000
#define E_EDGES 800000
#define HEADS 4
#define IN_DIM 256
#define HC 256
#define NEG_SLOPE 0.2f

// ---------------- device scratch ----------------
__device__ float g_h[N_NODES * HC];
__device__ float g_asrc[N_NODES * HEADS];
__device__ float g_adst[N_NODES * HEADS];
__device__ int   g_src[E_EDGES];
__device__ int   g_dst[E_EDGES];
__device__ int   g_deg[N_NODES];
__device__ int   g_rowstart[N_NODES + 1];
__device__ int   g_cursor[N_NODES];
__device__ int   g_csr[E_EDGES];
__device__ int   g_is64;
#define SCAN_BLK 1024
#define NSCAN ((N_NODES + SCAN_BLK - 1) / SCAN_BLK)   // 49
__device__ int   g_bsum[NSCAN];
__device__ int   g_boff[NSCAN];

// ---------------- dtype detection ----------------
__global__ void detect_kernel(const unsigned int* __restrict__ w) {
    __shared__ unsigned int r[256];
    unsigned int acc = 0;
    for (int i = threadIdx.x; i < 8192; i += 256) acc |= w[2 * i + 1];
    r[threadIdx.x] = acc;
    __syncthreads();
    if (threadIdx.x == 0) {
        unsigned int a = 0;
        #pragma unroll 8
        for (int i = 0; i < 256; i++) a |= r[i];
        g_is64 = (a == 0u) ? 1 : 0;
    }
}

__global__ void zero_deg_kernel() {
    int i = blockIdx.x * blockDim.x + threadIdx.x;
    if (i < N_NODES) g_deg[i] = 0;
}

__global__ void convert_kernel(const void* __restrict__ ei) {
    int e = blockIdx.x * blockDim.x + threadIdx.x;
    if (e >= E_EDGES) return;
    int s, d;
    if (g_is64) {
        const long long* p = (const long long*)ei;
        s = (int)p[e];
        d = (int)p[E_EDGES + e];
    } else {
        const int* p = (const int*)ei;
        s = p[e];
        d = p[E_EDGES + e];
    }
    g_src[e] = s;
    g_dst[e] = d;
    atomicAdd(&g_deg[d], 1);
}

// ---------------- TF32 GEMM 128x128, occ-2, fused attention dots ----------------
#define GBM 128
#define GBN 128
#define GBK 16
#define SSTR 136                       // 136 % 32 == 8 -> conflict-free fragment LDS
#define SFLOATS (GBK * SSTR)           // 2176

__device__ __forceinline__ float to_tf32(float x) {
    unsigned int r;
    asm("cvt.rna.tf32.f32 %0, %1;" : "=r"(r) : "f"(x));
    return __uint_as_float(r);
}

__device__ __forceinline__ void mma_tf32(float4& d, const float* a, const float* b) {
    asm volatile(
        "mma.sync.aligned.m16n8k8.row.col.f32.tf32.tf32.f32 "
        "{%0,%1,%2,%3}, {%4,%5,%6,%7}, {%8,%9}, {%0,%1,%2,%3};\n"
        : "+f"(d.x), "+f"(d.y), "+f"(d.z), "+f"(d.w)
        : "r"(__float_as_uint(a[0])), "r"(__float_as_uint(a[1])),
          "r"(__float_as_uint(a[2])), "r"(__float_as_uint(a[3])),
          "r"(__float_as_uint(b[0])), "r"(__float_as_uint(b[1])));
}

__global__ __launch_bounds__(256, 2) void sgemm_tf32_kernel(
    const float* __restrict__ x, const float* __restrict__ W,
    const float* __restrict__ att_src, const float* __restrict__ att_dst) {
    __shared__ __align__(16) float As[2][SFLOATS];
    __shared__ __align__(16) float Bs[2][SFLOATS];

    const int tid  = threadIdx.x;
    const int w    = tid >> 5;
    const int lane = tid & 31;
    const int gid  = lane >> 2;
    const int tig  = lane & 3;
    const int wm   = w & 3;    // 4 row groups of 32
    const int wn   = w >> 2;   // 2 col groups of 64
    const int rowblk = blockIdx.y * GBM;
    const int col0   = blockIdx.x * GBN;

    float4 acc[2][8];
    #pragma unroll
    for (int i = 0; i < 2; i++)
        #pragma unroll
        for (int j = 0; j < 8; j++) acc[i][j] = make_float4(0.f, 0.f, 0.f, 0.f);

    // staging regs
    float4 ar[2], br[2];
    // A loader: row = tid>>1 (0..127), k offset = (tid&1)*8, 2 float4 along k
    const int a_row = tid >> 1;
    const int a_kc  = (tid & 1) * 8;
    int a_grow = rowblk + a_row;
    if (a_grow > N_NODES - 1) a_grow = N_NODES - 1;
    // B loader: row kr = tid>>4 (0..15), col = (tid&15)*8, 2 float4 along n
    const int b_kr = tid >> 4;
    const int b_c  = (tid & 15) * 8;

    auto ldgA = [&](int k0) {
        const float* p = &x[(size_t)a_grow * IN_DIM + k0 + a_kc];
        ar[0] = *(const float4*)p;
        ar[1] = *(const float4*)(p + 4);
    };
    auto ldgB = [&](int k0) {
        const float* p = &W[(size_t)(k0 + b_kr) * HC + col0 + b_c];
        br[0] = *(const float4*)p;
        br[1] = *(const float4*)(p + 4);
    };
    auto stsA = [&](float* dst) {
        float v[8] = {ar[0].x, ar[0].y, ar[0].z, ar[0].w, ar[1].x, ar[1].y, ar[1].z, ar[1].w};
        #pragma unroll
        for (int j = 0; j < 8; j++)
            dst[(a_kc + j) * SSTR + a_row] = to_tf32(v[j]);
    };
    auto stsB = [&](float* dst) {
        float4 t0 = make_float4(to_tf32(br[0].x), to_tf32(br[0].y), to_tf32(br[0].z), to_tf32(br[0].w));
        float4 t1 = make_float4(to_tf32(br[1].x), to_tf32(br[1].y), to_tf32(br[1].z), to_tf32(br[1].w));
        *(float4*)&dst[b_kr * SSTR + b_c]     = t0;
        *(float4*)&dst[b_kr * SSTR + b_c + 4] = t1;
    };
    auto compute = [&](const float* Ac, const float* Bc) {
        #pragma unroll
        for (int ks = 0; ks < 2; ks++) {
            const int kb = ks * 8;
            float afr[2][4], bfr[8][2];
            #pragma unroll
            for (int mt = 0; mt < 2; mt++) {
                int mb = wm * 32 + mt * 16 + gid;
                afr[mt][0] = Ac[(kb + tig) * SSTR + mb];
                afr[mt][1] = Ac[(kb + tig) * SSTR + mb + 8];
                afr[mt][2] = Ac[(kb + tig + 4) * SSTR + mb];
                afr[mt][3] = Ac[(kb + tig + 4) * SSTR + mb + 8];
            }
            #pragma unroll
            for (int nt = 0; nt < 8; nt++) {
                int nb = wn * 64 + nt * 8 + gid;
                bfr[nt][0] = Bc[(kb + tig) * SSTR + nb];
                bfr[nt][1] = Bc[(kb + tig + 4) * SSTR + nb];
            }
            #pragma unroll
            for (int mt = 0; mt < 2; mt++)
                #pragma unroll
                for (int nt = 0; nt < 8; nt++)
                    mma_tf32(acc[mt][nt], afr[mt], bfr[nt]);
        }
    };

    // prologue
    ldgA(0); ldgB(0);
    stsA(As[0]); stsB(Bs[0]);
    ldgA(GBK); ldgB(GBK);
    __syncthreads();

    const int NIT = IN_DIM / GBK;   // 16
    for (int it = 0; it < NIT; ++it) {
        if (it + 1 < NIT) { stsA(As[(it + 1) & 1]); stsB(Bs[(it + 1) & 1]); }
        if (it + 2 < NIT) { ldgA((it + 2) * GBK); ldgB((it + 2) * GBK); }
        compute(As[it & 1], Bs[it & 1]);
        __syncthreads();
    }

    // epilogue: store h + fused attention dots (warp cols = one head)
    const int head = blockIdx.x * 2 + wn;
    float2 avs[8], avd[8];
    #pragma unroll
    for (int nt = 0; nt < 8; nt++) {
        int c = col0 + wn * 64 + nt * 8 + tig * 2;
        avs[nt] = *(const float2*)&att_src[c];
        avd[nt] = *(const float2*)&att_dst[c];
    }

    #pragma unroll
    for (int mt = 0; mt < 2; mt++) {
        int row0 = rowblk + wm * 32 + mt * 16 + gid;
        int row1 = row0 + 8;
        float s0 = 0.f, s1 = 0.f, t0 = 0.f, t1 = 0.f;
        #pragma unroll
        for (int nt = 0; nt < 8; nt++) {
            float4 d = acc[mt][nt];
            int col = col0 + wn * 64 + nt * 8 + tig * 2;
            if (row0 < N_NODES) *(float2*)&g_h[(size_t)row0 * HC + col] = make_float2(d.x, d.y);
            if (row1 < N_NODES) *(float2*)&g_h[(size_t)row1 * HC + col] = make_float2(d.z, d.w);
            s0 += d.x * avs[nt].x + d.y * avs[nt].y;
            s1 += d.z * avs[nt].x + d.w * avs[nt].y;
            t0 += d.x * avd[nt].x + d.y * avd[nt].y;
            t1 += d.z * avd[nt].x + d.w * avd[nt].y;
        }
        #pragma unroll
        for (int off = 1; off <= 2; off <<= 1) {
            s0 += __shfl_xor_sync(0xffffffffu, s0, off);
            s1 += __shfl_xor_sync(0xffffffffu, s1, off);
            t0 += __shfl_xor_sync(0xffffffffu, t0, off);
            t1 += __shfl_xor_sync(0xffffffffu, t1, off);
        }
        if (tig == 0) {
            if (row0 < N_NODES) { g_asrc[row0 * HEADS + head] = s0; g_adst[row0 * HEADS + head] = t0; }
            if (row1 < N_NODES) { g_asrc[row1 * HEADS + head] = s1; g_adst[row1 * HEADS + head] = t1; }
        }
    }
}

// ---------------- multi-block scan (3 tiny kernels) ----------------
__global__ void scan_reduce_kernel() {
    __shared__ int ws[32];
    int i = blockIdx.x * SCAN_BLK + threadIdx.x;
    int v = (i < N_NODES) ? g_deg[i] : 0;
    #pragma unroll
    for (int off = 16; off; off >>= 1) v += __shfl_xor_sync(0xffffffffu, v, off);
    if ((threadIdx.x & 31) == 0) ws[threadIdx.x >> 5] = v;
    __syncthreads();
    if (threadIdx.x < 32) {
        int t = ws[threadIdx.x];
        #pragma unroll
        for (int off = 16; off; off >>= 1) t += __shfl_xor_sync(0xffffffffu, t, off);
        if (threadIdx.x == 0) g_bsum[blockIdx.x] = t;
    }
}

__global__ void scan_offsets_kernel() {
    __shared__ int tmp[64];
    int t = threadIdx.x;
    int v = (t < NSCAN) ? g_bsum[t] : 0;
    tmp[t] = v;
    __syncthreads();
    #pragma unroll
    for (int off = 1; off < 64; off <<= 1) {
        int a = (t >= off) ? tmp[t - off] : 0;
        __syncthreads();
        tmp[t] += a;
        __syncthreads();
    }
    if (t < NSCAN) g_boff[t] = tmp[t] - v;   // exclusive
    if (t == NSCAN - 1) g_rowstart[N_NODES] = tmp[t];
}

__global__ void scan_local_kernel() {
    __shared__ int wsums[32];
    const int tid = threadIdx.x, wid = tid >> 5, lane = tid & 31;
    int i = blockIdx.x * SCAN_BLK + tid;
    int v = (i < N_NODES) ? g_deg[i] : 0;
    int incl = v;
    #pragma unroll
    for (int off = 1; off < 32; off <<= 1) {
        int t = __shfl_up_sync(0xffffffffu, incl, off);
        if (lane >= off) incl += t;
    }
    if (lane == 31) wsums[wid] = incl;
    __syncthreads();
    if (wid == 0) {
        int wv = wsums[lane];
        #pragma unroll
        for (int off = 1; off < 32; off <<= 1) {
            int t = __shfl_up_sync(0xffffffffu, wv, off);
            if (lane >= off) wv += t;
        }
        wsums[lane] = wv;
    }
    __syncthreads();
    if (i < N_NODES) {
        int start = g_boff[blockIdx.x] + ((wid > 0) ? wsums[wid - 1] : 0) + incl - v;
        g_rowstart[i] = start;
        g_cursor[i]   = start;
    }
}

__global__ void fill_kernel() {
    int e = blockIdx.x * blockDim.x + threadIdx.x;
    if (e < E_EDGES) {
        int d = g_dst[e];
        int slot = atomicAdd(&g_cursor[d], 1);
        g_csr[slot] = g_src[e];
    }
}

// ---------------- fused softmax + gather + bias + relu ----------------
#define CAP 96
__global__ __launch_bounds__(256) void gat_node_kernel(const float* __restrict__ bias,
                                                       float* __restrict__ out) {
    __shared__ float s_lg[8][CAP][4];
    __shared__ int   s_src[8][CAP];

    const int w    = threadIdx.x >> 5;
    const int lane = threadIdx.x & 31;
    const int node = (blockIdx.x * blockDim.x + threadIdx.x) >> 5;
    if (node >= N_NODES) return;
    const int n   = node;
    const int rs  = g_rowstart[n];
    const int deg = g_rowstart[n + 1] - rs;
    const int tot = deg + 1;

    float4 ad4 = *(const float4*)&g_adst[n * HEADS];
    float ad[4] = {ad4.x, ad4.y, ad4.z, ad4.w};
    const int myh = lane >> 3;

    float acc[8] = {0.f, 0.f, 0.f, 0.f, 0.f, 0.f, 0.f, 0.f};

    if (tot <= CAP) {
        float m[4] = {-CUDART_INF_F, -CUDART_INF_F, -CUDART_INF_F, -CUDART_INF_F};
        for (int i = lane; i < tot; i += 32) {
            int src = (i < deg) ? g_csr[rs + i] : n;
            s_src[w][i] = src;
            float4 a4 = *(const float4*)&g_asrc[src * HEADS];
            float lg[4] = {a4.x + ad[0], a4.y + ad[1], a4.z + ad[2], a4.w + ad[3]};
            #pragma unroll
            for (int h = 0; h < 4; h++) {
                lg[h] = lg[h] >= 0.f ? lg[h] : NEG_SLOPE * lg[h];
                m[h] = fmaxf(m[h], lg[h]);
            }
            *(float4*)&s_lg[w][i][0] = make_float4(lg[0], lg[1], lg[2], lg[3]);
        }
        #pragma unroll
        for (int off = 16; off; off >>= 1)
            #pragma unroll
            for (int h = 0; h < 4; h++)
                m[h] = fmaxf(m[h], __shfl_xor_sync(0xffffffffu, m[h], off));

        float s[4] = {0.f, 0.f, 0.f, 0.f};
        for (int i = lane; i < tot; i += 32) {
            float4 L = *(const float4*)&s_lg[w][i][0];
            float e0 = __expf(L.x - m[0]);
            float e1 = __expf(L.y - m[1]);
            float e2 = __expf(L.z - m[2]);
            float e3 = __expf(L.w - m[3]);
            s[0] += e0; s[1] += e1; s[2] += e2; s[3] += e3;
            *(float4*)&s_lg[w][i][0] = make_float4(e0, e1, e2, e3);
        }
        #pragma unroll
        for (int off = 16; off; off >>= 1)
            #pragma unroll
            for (int h = 0; h < 4; h++)
                s[h] += __shfl_xor_sync(0xffffffffu, s[h], off);

        const float inv = 1.f / (s[myh] + 1e-16f);
        __syncwarp();

        // feature gather, unroll x4
        int i = 0;
        for (; i + 4 <= tot; i += 4) {
            int   sA = s_src[w][i],     sB = s_src[w][i + 1];
            int   sC = s_src[w][i + 2], sD = s_src[w][i + 3];
            float aA = s_lg[w][i][myh] * inv,     aB = s_lg[w][i + 1][myh] * inv;
            float aC = s_lg[w][i + 2][myh] * inv, aD = s_lg[w][i + 3][myh] * inv;
            const float4* pA = (const float4*)&g_h[(size_t)sA * HC + lane * 8];
            const float4* pB = (const float4*)&g_h[(size_t)sB * HC + lane * 8];
            const float4* pC = (const float4*)&g_h[(size_t)sC * HC + lane * 8];
            const float4* pD = (const float4*)&g_h[(size_t)sD * HC + lane * 8];
            float4 A0 = pA[0], A1 = pA[1], B0 = pB[0], B1 = pB[1];
            float4 C0 = pC[0], C1 = pC[1], D0 = pD[0], D1 = pD[1];
            acc[0] += aA * A0.x + aB * B0.x + aC * C0.x + aD * D0.x;
            acc[1] += aA * A0.y + aB * B0.y + aC * C0.y + aD * D0.y;
            acc[2] += aA * A0.z + aB * B0.z + aC * C0.z + aD * D0.z;
            acc[3] += aA * A0.w + aB * B0.w + aC * C0.w + aD * D0.w;
            acc[4] += aA * A1.x + aB * B1.x + aC * C1.x + aD * D1.x;
            acc[5] += aA * A1.y + aB * B1.y + aC * C1.y + aD * D1.y;
            acc[6] += aA * A1.z + aB * B1.z + aC * C1.z + aD * D1.z;
            acc[7] += aA * A1.w + aB * B1.w + aC * C1.w + aD * D1.w;
        }
        for (; i < tot; i++) {
            int   s0 = s_src[w][i];
            float a0 = s_lg[w][i][myh] * inv;
            const float4* p0 = (const float4*)&g_h[(size_t)s0 * HC + lane * 8];
            float4 f0 = p0[0], f1 = p0[1];
            acc[0] += a0 * f0.x; acc[1] += a0 * f0.y;
            acc[2] += a0 * f0.z; acc[3] += a0 * f0.w;
            acc[4] += a0 * f1.x; acc[5] += a0 * f1.y;
            acc[6] += a0 * f1.z; acc[7] += a0 * f1.w;
        }
    } else {
        // fallback: 3 global passes
        float m[4] = {-CUDART_INF_F, -CUDART_INF_F, -CUDART_INF_F, -CUDART_INF_F};
        for (int i = lane; i < tot; i += 32) {
            int src = (i < deg) ? g_csr[rs + i] : n;
            float4 a4 = *(const float4*)&g_asrc[src * HEADS];
            float lg[4] = {a4.x + ad[0], a4.y + ad[1], a4.z + ad[2], a4.w + ad[3]};
            #pragma unroll
            for (int h = 0; h < 4; h++) {
                float v = lg[h] >= 0.f ? lg[h] : NEG_SLOPE * lg[h];
                m[h] = fmaxf(m[h], v);
            }
        }
        #pragma unroll
        for (int off = 16; off; off >>= 1)
            #pragma unroll
            for (int h = 0; h < 4; h++)
                m[h] = fmaxf(m[h], __shfl_xor_sync(0xffffffffu, m[h], off));

        float s[4] = {0.f, 0.f, 0.f, 0.f};
        for (int i = lane; i < tot; i += 32) {
            int src = (i < deg) ? g_csr[rs + i] : n;
            float4 a4 = *(const float4*)&g_asrc[src * HEADS];
            float lg[4] = {a4.x + ad[0], a4.y + ad[1], a4.z + ad[2], a4.w + ad[3]};
            #pragma unroll
            for (int h = 0; h < 4; h++) {
                float v = lg[h] >= 0.f ? lg[h] : NEG_SLOPE * lg[h];
                s[h] += __expf(v - m[h]);
            }
        }
        #pragma unroll
        for (int off = 16; off; off >>= 1)
            #pragma unroll
            for (int h = 0; h < 4; h++)
                s[h] += __shfl_xor_sync(0xffffffffu, s[h], off);

        const float mh  = m[myh];
        const float inv = 1.f / (s[myh] + 1e-16f);
        const float adh = ad[myh];
        for (int i = 0; i < tot; i++) {
            int src = (i < deg) ? g_csr[rs + i] : n;
            float av = g_asrc[src * HEADS + myh];
            float lg = av + adh;
            lg = lg >= 0.f ? lg : NEG_SLOPE * lg;
            float alpha = __expf(lg - mh) * inv;
            const float4* hp = (const float4*)&g_h[(size_t)src * HC + lane * 8];
            float4 f0 = hp[0], f1 = hp[1];
            acc[0] += alpha * f0.x; acc[1] += alpha * f0.y;
            acc[2] += alpha * f0.z; acc[3] += alpha * f0.w;
            acc[4] += alpha * f1.x; acc[5] += alpha * f1.y;
            acc[6] += alpha * f1.z; acc[7] += alpha * f1.w;
        }
    }

    float4 b0 = ((const float4*)bias)[lane * 2];
    float4 b1 = ((const float4*)bias)[lane * 2 + 1];
    float4 o0, o1;
    o0.x = fmaxf(acc[0] + b0.x, 0.f); o0.y = fmaxf(acc[1] + b0.y, 0.f);
    o0.z = fmaxf(acc[2] + b0.z, 0.f); o0.w = fmaxf(acc[3] + b0.w, 0.f);
    o1.x = fmaxf(acc[4] + b1.x, 0.f); o1.y = fmaxf(acc[5] + b1.y, 0.f);
    o1.z = fmaxf(acc[6] + b1.z, 0.f); o1.w = fmaxf(acc[7] + b1.w, 0.f);
    *(float4*)&out[(size_t)n * HC + lane * 8]     = o0;
    *(float4*)&out[(size_t)n * HC + lane * 8 + 4] = o1;
}

// ---------------- launch ----------------
extern "C" void kernel_launch(void* const* d_in, const int* in_sizes, int n_in,
                              void* d_out, int out_size) {
    const float* x       = (const float*)d_in[0];
    const void*  ei      = d_in[1];
    const float* W       = (const float*)d_in[2];
    const float* att_src = (const float*)d_in[3];
    const float* att_dst = (const float*)d_in[4];
    const float* bias    = (const float*)d_in[5];
    float*       out     = (float*)d_out;

    detect_kernel<<<1, 256>>>((const unsigned int*)ei);
    zero_deg_kernel<<<(N_NODES + 255) / 256, 256>>>();
    convert_kernel<<<(E_EDGES + 255) / 256, 256>>>(ei);

    dim3 gg(HC / GBN, (N_NODES + GBM - 1) / GBM);   // (2, 391)
    sgemm_tf32_kernel<<<gg, 256>>>(x, W, att_src, att_dst);

    scan_reduce_kernel<<<NSCAN, SCAN_BLK>>>();
    scan_offsets_kernel<<<1, 64>>>();
    scan_local_kernel<<<NSCAN, SCAN_BLK>>>();
    fill_kernel<<<(E_EDGES + 255) / 256, 256>>>();

    gat_node_kernel<<<(N_NODES + 7) / 8, 256>>>(bias, out);
}

// round 4
// speedup vs baseline: 1.8836x; 1.0209x over previous
#include <cuda_runtime.h>
#include <math_constants.h>
#include <cstdint>

#define N_NODES 50000
#define E_EDGES 800000
#define HEADS 4
#define IN_DIM 256
#define HC 256
#define NEG_SLOPE 0.2f

// ---------------- device scratch ----------------
__device__ float g_h[N_NODES * HC];
__device__ float g_wt[IN_DIM * HC];          // W transposed: [n][k]
__device__ float g_asrc[N_NODES * HEADS];
__device__ float g_adst[N_NODES * HEADS];
__device__ int   g_src[E_EDGES];
__device__ int   g_dst[E_EDGES];
__device__ int   g_deg[N_NODES];
__device__ int   g_rowstart[N_NODES + 1];
__device__ int   g_cursor[N_NODES];
__device__ int   g_csr[E_EDGES];
__device__ int   g_is64;
#define SCAN_BLK 1024
#define NSCAN ((N_NODES + SCAN_BLK - 1) / SCAN_BLK)   // 49
__device__ int   g_bsum[NSCAN];
__device__ int   g_boff[NSCAN];

// ---------------- dtype detection ----------------
__global__ void detect_kernel(const unsigned int* __restrict__ w) {
    __shared__ unsigned int r[256];
    unsigned int acc = 0;
    for (int i = threadIdx.x; i < 8192; i += 256) acc |= w[2 * i + 1];
    r[threadIdx.x] = acc;
    __syncthreads();
    if (threadIdx.x == 0) {
        unsigned int a = 0;
        #pragma unroll 8
        for (int i = 0; i < 256; i++) a |= r[i];
        g_is64 = (a == 0u) ? 1 : 0;
    }
}

__global__ void zero_deg_kernel() {
    int i = blockIdx.x * blockDim.x + threadIdx.x;
    if (i < N_NODES) g_deg[i] = 0;
}

__global__ void convert_kernel(const void* __restrict__ ei) {
    int e = blockIdx.x * blockDim.x + threadIdx.x;
    if (e >= E_EDGES) return;
    int s, d;
    if (g_is64) {
        const long long* p = (const long long*)ei;
        s = (int)p[e];
        d = (int)p[E_EDGES + e];
    } else {
        const int* p = (const int*)ei;
        s = p[e];
        d = p[E_EDGES + e];
    }
    g_src[e] = s;
    g_dst[e] = d;
    atomicAdd(&g_deg[d], 1);
}

// ---------------- W transpose (256x256) ----------------
__global__ void transpose_w_kernel(const float* __restrict__ W) {
    __shared__ float t[32][33];
    const int bx = blockIdx.x * 32, by = blockIdx.y * 32;
    #pragma unroll
    for (int i = 0; i < 4; i++)
        t[threadIdx.y + i * 8][threadIdx.x] = W[(by + threadIdx.y + i * 8) * HC + bx + threadIdx.x];
    __syncthreads();
    #pragma unroll
    for (int i = 0; i < 4; i++)
        g_wt[(bx + threadIdx.y + i * 8) * IN_DIM + by + threadIdx.x] = t[threadIdx.x][threadIdx.y + i * 8];
}

// ---------------- TF32 GEMM 128x128, ldmatrix fragments ----------------
#define GBM 128
#define GBN 128
#define GBK 16
// tile layout: 128 rows x 16 tf32 (64B rows), chunk-XOR swizzle
#define TILE_FLOATS (128 * 16)

__device__ __forceinline__ float to_tf32(float x) {
    unsigned int r;
    asm("cvt.rna.tf32.f32 %0, %1;" : "=r"(r) : "f"(x));
    return __uint_as_float(r);
}

__device__ __forceinline__ void ldsm_x4(uint32_t addr, uint32_t& r0, uint32_t& r1,
                                        uint32_t& r2, uint32_t& r3) {
    asm volatile("ldmatrix.sync.aligned.m8n8.x4.shared.b16 {%0,%1,%2,%3}, [%4];"
                 : "=r"(r0), "=r"(r1), "=r"(r2), "=r"(r3) : "r"(addr));
}

__device__ __forceinline__ void mma_tf32(float4& d, const uint32_t* a, const uint32_t* b) {
    asm volatile(
        "mma.sync.aligned.m16n8k8.row.col.f32.tf32.tf32.f32 "
        "{%0,%1,%2,%3}, {%4,%5,%6,%7}, {%8,%9}, {%0,%1,%2,%3};\n"
        : "+f"(d.x), "+f"(d.y), "+f"(d.z), "+f"(d.w)
        : "r"(a[0]), "r"(a[1]), "r"(a[2]), "r"(a[3]),
          "r"(b[0]), "r"(b[1]));
}

__global__ __launch_bounds__(256, 2) void sgemm_tf32_kernel(
    const float* __restrict__ x,
    const float* __restrict__ att_src, const float* __restrict__ att_dst) {
    __shared__ __align__(16) float As[2][TILE_FLOATS];
    __shared__ __align__(16) float Bs[2][TILE_FLOATS];

    const int tid  = threadIdx.x;
    const int w    = tid >> 5;
    const int lane = tid & 31;
    const int gid  = lane >> 2;
    const int tig  = lane & 3;
    const int wm   = w & 3;    // 4 row groups of 32
    const int wn   = w >> 2;   // 2 col groups of 64
    const int rowblk = blockIdx.y * GBM;
    const int col0   = blockIdx.x * GBN;

    float4 acc[2][8];
    #pragma unroll
    for (int i = 0; i < 2; i++)
        #pragma unroll
        for (int j = 0; j < 8; j++) acc[i][j] = make_float4(0.f, 0.f, 0.f, 0.f);

    // ---- loader indices: row = tid>>1 (0..127), 8 k per thread ----
    const int l_row = tid >> 1;
    const int l_kc  = (tid & 1) * 8;
    int a_grow = rowblk + l_row;
    if (a_grow > N_NODES - 1) a_grow = N_NODES - 1;
    const int b_grow = col0 + l_row;

    // STS offsets (floats), chunk-XOR swizzle: chunk ^= (row>>1)&3
    const int swq   = (l_row >> 1) & 3;
    const int c0    = (tid & 1) * 2;
    const int sts0  = l_row * 16 + ((c0 ^ swq) << 2);
    const int sts1  = l_row * 16 + (((c0 + 1) ^ swq) << 2);

    // ldmatrix lane offsets (bytes): lane -> (row-in-16, chunk-sel)
    const int lr  = (lane & 7) | (lane & 8);   // 0..15
    const int csl = lane >> 4;                  // 0/1
    const int q2  = (lr >> 1) & 3;
    const uint32_t loff0 = lr * 64 + (((0 + csl) ^ q2) << 4);  // kb=0 (chunks 0,1)
    const uint32_t loff1 = lr * 64 + (((2 + csl) ^ q2) << 4);  // kb=8 (chunks 2,3)

    const uint32_t aB0 = (uint32_t)__cvta_generic_to_shared(&As[0][0]);
    const uint32_t aB1 = (uint32_t)__cvta_generic_to_shared(&As[1][0]);
    const uint32_t bB0 = (uint32_t)__cvta_generic_to_shared(&Bs[0][0]);
    const uint32_t bB1 = (uint32_t)__cvta_generic_to_shared(&Bs[1][0]);

    float4 ar0, ar1, br0, br1;
    auto ldgA = [&](int k0) {
        const float* p = &x[(size_t)a_grow * IN_DIM + k0 + l_kc];
        ar0 = *(const float4*)p;
        ar1 = *(const float4*)(p + 4);
    };
    auto ldgB = [&](int k0) {
        const float* p = &g_wt[(size_t)b_grow * IN_DIM + k0 + l_kc];
        br0 = *(const float4*)p;
        br1 = *(const float4*)(p + 4);
    };
    auto stsA = [&](int buf) {
        float* d = As[buf];
        *(float4*)&d[sts0] = make_float4(to_tf32(ar0.x), to_tf32(ar0.y), to_tf32(ar0.z), to_tf32(ar0.w));
        *(float4*)&d[sts1] = make_float4(to_tf32(ar1.x), to_tf32(ar1.y), to_tf32(ar1.z), to_tf32(ar1.w));
    };
    auto stsB = [&](int buf) {
        float* d = Bs[buf];
        *(float4*)&d[sts0] = make_float4(to_tf32(br0.x), to_tf32(br0.y), to_tf32(br0.z), to_tf32(br0.w));
        *(float4*)&d[sts1] = make_float4(to_tf32(br1.x), to_tf32(br1.y), to_tf32(br1.z), to_tf32(br1.w));
    };

    auto compute = [&](int buf) {
        const uint32_t Ab = buf ? aB1 : aB0;
        const uint32_t Bb = buf ? bB1 : bB0;
        #pragma unroll
        for (int kbi = 0; kbi < 2; kbi++) {
            const uint32_t lo = kbi ? loff1 : loff0;
            uint32_t afr[2][4], bfr[8][2];
            #pragma unroll
            for (int mt = 0; mt < 2; mt++) {
                uint32_t addr = Ab + (uint32_t)((wm * 32 + mt * 16) * 64) + lo;
                ldsm_x4(addr, afr[mt][0], afr[mt][1], afr[mt][2], afr[mt][3]);
            }
            #pragma unroll
            for (int ntp = 0; ntp < 4; ntp++) {
                uint32_t addr = Bb + (uint32_t)((wn * 64 + ntp * 16) * 64) + lo;
                ldsm_x4(addr, bfr[2 * ntp][0], bfr[2 * ntp + 1][0],
                              bfr[2 * ntp][1], bfr[2 * ntp + 1][1]);
            }
            #pragma unroll
            for (int mt = 0; mt < 2; mt++)
                #pragma unroll
                for (int nt = 0; nt < 8; nt++)
                    mma_tf32(acc[mt][nt], afr[mt], bfr[nt]);
        }
    };

    // prologue
    ldgA(0); ldgB(0);
    stsA(0); stsB(0);
    ldgA(GBK); ldgB(GBK);
    __syncthreads();

    const int NIT = IN_DIM / GBK;   // 16
    for (int it = 0; it < NIT; ++it) {
        if (it + 1 < NIT) { stsA((it + 1) & 1); stsB((it + 1) & 1); }
        if (it + 2 < NIT) { ldgA((it + 2) * GBK); ldgB((it + 2) * GBK); }
        compute(it & 1);
        __syncthreads();
    }

    // epilogue: store h + fused attention dots (warp cols = one head)
    const int head = blockIdx.x * 2 + wn;
    float2 avs[8], avd[8];
    #pragma unroll
    for (int nt = 0; nt < 8; nt++) {
        int c = col0 + wn * 64 + nt * 8 + tig * 2;
        avs[nt] = *(const float2*)&att_src[c];
        avd[nt] = *(const float2*)&att_dst[c];
    }

    #pragma unroll
    for (int mt = 0; mt < 2; mt++) {
        int row0 = rowblk + wm * 32 + mt * 16 + gid;
        int row1 = row0 + 8;
        float s0 = 0.f, s1 = 0.f, t0 = 0.f, t1 = 0.f;
        #pragma unroll
        for (int nt = 0; nt < 8; nt++) {
            float4 d = acc[mt][nt];
            int col = col0 + wn * 64 + nt * 8 + tig * 2;
            if (row0 < N_NODES) *(float2*)&g_h[(size_t)row0 * HC + col] = make_float2(d.x, d.y);
            if (row1 < N_NODES) *(float2*)&g_h[(size_t)row1 * HC + col] = make_float2(d.z, d.w);
            s0 += d.x * avs[nt].x + d.y * avs[nt].y;
            s1 += d.z * avs[nt].x + d.w * avs[nt].y;
            t0 += d.x * avd[nt].x + d.y * avd[nt].y;
            t1 += d.z * avd[nt].x + d.w * avd[nt].y;
        }
        #pragma unroll
        for (int off = 1; off <= 2; off <<= 1) {
            s0 += __shfl_xor_sync(0xffffffffu, s0, off);
            s1 += __shfl_xor_sync(0xffffffffu, s1, off);
            t0 += __shfl_xor_sync(0xffffffffu, t0, off);
            t1 += __shfl_xor_sync(0xffffffffu, t1, off);
        }
        if (tig == 0) {
            if (row0 < N_NODES) { g_asrc[row0 * HEADS + head] = s0; g_adst[row0 * HEADS + head] = t0; }
            if (row1 < N_NODES) { g_asrc[row1 * HEADS + head] = s1; g_adst[row1 * HEADS + head] = t1; }
        }
    }
}

// ---------------- multi-block scan ----------------
__global__ void scan_reduce_kernel() {
    __shared__ int ws[32];
    int i = blockIdx.x * SCAN_BLK + threadIdx.x;
    int v = (i < N_NODES) ? g_deg[i] : 0;
    #pragma unroll
    for (int off = 16; off; off >>= 1) v += __shfl_xor_sync(0xffffffffu, v, off);
    if ((threadIdx.x & 31) == 0) ws[threadIdx.x >> 5] = v;
    __syncthreads();
    if (threadIdx.x < 32) {
        int t = ws[threadIdx.x];
        #pragma unroll
        for (int off = 16; off; off >>= 1) t += __shfl_xor_sync(0xffffffffu, t, off);
        if (threadIdx.x == 0) g_bsum[blockIdx.x] = t;
    }
}

__global__ void scan_offsets_kernel() {
    __shared__ int tmp[64];
    int t = threadIdx.x;
    int v = (t < NSCAN) ? g_bsum[t] : 0;
    tmp[t] = v;
    __syncthreads();
    #pragma unroll
    for (int off = 1; off < 64; off <<= 1) {
        int a = (t >= off) ? tmp[t - off] : 0;
        __syncthreads();
        tmp[t] += a;
        __syncthreads();
    }
    if (t < NSCAN) g_boff[t] = tmp[t] - v;
    if (t == NSCAN - 1) g_rowstart[N_NODES] = tmp[t];
}

__global__ void scan_local_kernel() {
    __shared__ int wsums[32];
    const int tid = threadIdx.x, wid = tid >> 5, lane = tid & 31;
    int i = blockIdx.x * SCAN_BLK + tid;
    int v = (i < N_NODES) ? g_deg[i] : 0;
    int incl = v;
    #pragma unroll
    for (int off = 1; off < 32; off <<= 1) {
        int t = __shfl_up_sync(0xffffffffu, incl, off);
        if (lane >= off) incl += t;
    }
    if (lane == 31) wsums[wid] = incl;
    __syncthreads();
    if (wid == 0) {
        int wv = wsums[lane];
        #pragma unroll
        for (int off = 1; off < 32; off <<= 1) {
            int t = __shfl_up_sync(0xffffffffu, wv, off);
            if (lane >= off) wv += t;
        }
        wsums[lane] = wv;
    }
    __syncthreads();
    if (i < N_NODES) {
        int start = g_boff[blockIdx.x] + ((wid > 0) ? wsums[wid - 1] : 0) + incl - v;
        g_rowstart[i] = start;
        g_cursor[i]   = start;
    }
}

__global__ void fill_kernel() {
    int e = blockIdx.x * blockDim.x + threadIdx.x;
    if (e < E_EDGES) {
        int d = g_dst[e];
        int slot = atomicAdd(&g_cursor[d], 1);
        g_csr[slot] = g_src[e];
    }
}

// ---------------- fused softmax + gather + bias + relu ----------------
#define CAP 96
__global__ __launch_bounds__(256) void gat_node_kernel(const float* __restrict__ bias,
                                                       float* __restrict__ out) {
    __shared__ float s_lg[8][CAP][4];
    __shared__ int   s_src[8][CAP];

    const int w    = threadIdx.x >> 5;
    const int lane = threadIdx.x & 31;
    const int node = (blockIdx.x * blockDim.x + threadIdx.x) >> 5;
    if (node >= N_NODES) return;
    const int n   = node;
    const int rs  = g_rowstart[n];
    const int deg = g_rowstart[n + 1] - rs;
    const int tot = deg + 1;

    float4 ad4 = *(const float4*)&g_adst[n * HEADS];
    float ad[4] = {ad4.x, ad4.y, ad4.z, ad4.w};
    const int myh = lane >> 3;

    float acc[8] = {0.f, 0.f, 0.f, 0.f, 0.f, 0.f, 0.f, 0.f};

    if (tot <= CAP) {
        float m[4] = {-CUDART_INF_F, -CUDART_INF_F, -CUDART_INF_F, -CUDART_INF_F};
        for (int i = lane; i < tot; i += 32) {
            int src = (i < deg) ? g_csr[rs + i] : n;
            s_src[w][i] = src;
            float4 a4 = *(const float4*)&g_asrc[src * HEADS];
            float lg[4] = {a4.x + ad[0], a4.y + ad[1], a4.z + ad[2], a4.w + ad[3]};
            #pragma unroll
            for (int h = 0; h < 4; h++) {
                lg[h] = lg[h] >= 0.f ? lg[h] : NEG_SLOPE * lg[h];
                m[h] = fmaxf(m[h], lg[h]);
            }
            *(float4*)&s_lg[w][i][0] = make_float4(lg[0], lg[1], lg[2], lg[3]);
        }
        #pragma unroll
        for (int off = 16; off; off >>= 1)
            #pragma unroll
            for (int h = 0; h < 4; h++)
                m[h] = fmaxf(m[h], __shfl_xor_sync(0xffffffffu, m[h], off));

        float s[4] = {0.f, 0.f, 0.f, 0.f};
        for (int i = lane; i < tot; i += 32) {
            float4 L = *(const float4*)&s_lg[w][i][0];
            float e0 = __expf(L.x - m[0]);
            float e1 = __expf(L.y - m[1]);
            float e2 = __expf(L.z - m[2]);
            float e3 = __expf(L.w - m[3]);
            s[0] += e0; s[1] += e1; s[2] += e2; s[3] += e3;
            *(float4*)&s_lg[w][i][0] = make_float4(e0, e1, e2, e3);
        }
        #pragma unroll
        for (int off = 16; off; off >>= 1)
            #pragma unroll
            for (int h = 0; h < 4; h++)
                s[h] += __shfl_xor_sync(0xffffffffu, s[h], off);

        const float inv = 1.f / (s[myh] + 1e-16f);
        __syncwarp();

        int i = 0;
        for (; i + 4 <= tot; i += 4) {
            int   sA = s_src[w][i],     sB = s_src[w][i + 1];
            int   sC = s_src[w][i + 2], sD = s_src[w][i + 3];
            float aA = s_lg[w][i][myh] * inv,     aB = s_lg[w][i + 1][myh] * inv;
            float aC = s_lg[w][i + 2][myh] * inv, aD = s_lg[w][i + 3][myh] * inv;
            const float4* pA = (const float4*)&g_h[(size_t)sA * HC + lane * 8];
            const float4* pB = (const float4*)&g_h[(size_t)sB * HC + lane * 8];
            const float4* pC = (const float4*)&g_h[(size_t)sC * HC + lane * 8];
            const float4* pD = (const float4*)&g_h[(size_t)sD * HC + lane * 8];
            float4 A0 = pA[0], A1 = pA[1], B0 = pB[0], B1 = pB[1];
            float4 C0 = pC[0], C1 = pC[1], D0 = pD[0], D1 = pD[1];
            acc[0] += aA * A0.x + aB * B0.x + aC * C0.x + aD * D0.x;
            acc[1] += aA * A0.y + aB * B0.y + aC * C0.y + aD * D0.y;
            acc[2] += aA * A0.z + aB * B0.z + aC * C0.z + aD * D0.z;
            acc[3] += aA * A0.w + aB * B0.w + aC * C0.w + aD * D0.w;
            acc[4] += aA * A1.x + aB * B1.x + aC * C1.x + aD * D1.x;
            acc[5] += aA * A1.y + aB * B1.y + aC * C1.y + aD * D1.y;
            acc[6] += aA * A1.z + aB * B1.z + aC * C1.z + aD * D1.z;
            acc[7] += aA * A1.w + aB * B1.w + aC * C1.w + aD * D1.w;
        }
        for (; i < tot; i++) {
            int   s0 = s_src[w][i];
            float a0 = s_lg[w][i][myh] * inv;
            const float4* p0 = (const float4*)&g_h[(size_t)s0 * HC + lane * 8];
            float4 f0 = p0[0], f1 = p0[1];
            acc[0] += a0 * f0.x; acc[1] += a0 * f0.y;
            acc[2] += a0 * f0.z; acc[3] += a0 * f0.w;
            acc[4] += a0 * f1.x; acc[5] += a0 * f1.y;
            acc[6] += a0 * f1.z; acc[7] += a0 * f1.w;
        }
    } else {
        float m[4] = {-CUDART_INF_F, -CUDART_INF_F, -CUDART_INF_F, -CUDART_INF_F};
        for (int i = lane; i < tot; i += 32) {
            int src = (i < deg) ? g_csr[rs + i] : n;
            float4 a4 = *(const float4*)&g_asrc[src * HEADS];
            float lg[4] = {a4.x + ad[0], a4.y + ad[1], a4.z + ad[2], a4.w + ad[3]};
            #pragma unroll
            for (int h = 0; h < 4; h++) {
                float v = lg[h] >= 0.f ? lg[h] : NEG_SLOPE * lg[h];
                m[h] = fmaxf(m[h], v);
            }
        }
        #pragma unroll
        for (int off = 16; off; off >>= 1)
            #pragma unroll
            for (int h = 0; h < 4; h++)
                m[h] = fmaxf(m[h], __shfl_xor_sync(0xffffffffu, m[h], off));

        float s[4] = {0.f, 0.f, 0.f, 0.f};
        for (int i = lane; i < tot; i += 32) {
            int src = (i < deg) ? g_csr[rs + i] : n;
            float4 a4 = *(const float4*)&g_asrc[src * HEADS];
            float lg[4] = {a4.x + ad[0], a4.y + ad[1], a4.z + ad[2], a4.w + ad[3]};
            #pragma unroll
            for (int h = 0; h < 4; h++) {
                float v = lg[h] >= 0.f ? lg[h] : NEG_SLOPE * lg[h];
                s[h] += __expf(v - m[h]);
            }
        }
        #pragma unroll
        for (int off = 16; off; off >>= 1)
            #pragma unroll
            for (int h = 0; h < 4; h++)
                s[h] += __shfl_xor_sync(0xffffffffu, s[h], off);

        const float mh  = m[myh];
        const float inv = 1.f / (s[myh] + 1e-16f);
        const float adh = ad[myh];
        for (int i = 0; i < tot; i++) {
            int src = (i < deg) ? g_csr[rs + i] : n;
            float av = g_asrc[src * HEADS + myh];
            float lg = av + adh;
            lg = lg >= 0.f ? lg : NEG_SLOPE * lg;
            float alpha = __expf(lg - mh) * inv;
            const float4* hp = (const float4*)&g_h[(size_t)src * HC + lane * 8];
            float4 f0 = hp[0], f1 = hp[1];
            acc[0] += alpha * f0.x; acc[1] += alpha * f0.y;
            acc[2] += alpha * f0.z; acc[3] += alpha * f0.w;
            acc[4] += alpha * f1.x; acc[5] += alpha * f1.y;
            acc[6] += alpha * f1.z; acc[7] += alpha * f1.w;
        }
    }

    float4 b0 = ((const float4*)bias)[lane * 2];
    float4 b1 = ((const float4*)bias)[lane * 2 + 1];
    float4 o0, o1;
    o0.x = fmaxf(acc[0] + b0.x, 0.f); o0.y = fmaxf(acc[1] + b0.y, 0.f);
    o0.z = fmaxf(acc[2] + b0.z, 0.f); o0.w = fmaxf(acc[3] + b0.w, 0.f);
    o1.x = fmaxf(acc[4] + b1.x, 0.f); o1.y = fmaxf(acc[5] + b1.y, 0.f);
    o1.z = fmaxf(acc[6] + b1.z, 0.f); o1.w = fmaxf(acc[7] + b1.w, 0.f);
    *(float4*)&out[(size_t)n * HC + lane * 8]     = o0;
    *(float4*)&out[(size_t)n * HC + lane * 8 + 4] = o1;
}

// ---------------- launch ----------------
extern "C" void kernel_launch(void* const* d_in, const int* in_sizes, int n_in,
                              void* d_out, int out_size) {
    const float* x       = (const float*)d_in[0];
    const void*  ei      = d_in[1];
    const float* W       = (const float*)d_in[2];
    const float* att_src = (const float*)d_in[3];
    const float* att_dst = (const float*)d_in[4];
    const float* bias    = (const float*)d_in[5];
    float*       out     = (float*)d_out;

    detect_kernel<<<1, 256>>>((const unsigned int*)ei);
    zero_deg_kernel<<<(N_NODES + 255) / 256, 256>>>();
    convert_kernel<<<(E_EDGES + 255) / 256, 256>>>(ei);

    dim3 tg(8, 8);
    transpose_w_kernel<<<tg, dim3(32, 8)>>>(W);

    dim3 gg(HC / GBN, (N_NODES + GBM - 1) / GBM);   // (2, 391)
    sgemm_tf32_kernel<<<gg, 256>>>(x, att_src, att_dst);

    scan_reduce_kernel<<<NSCAN, SCAN_BLK>>>();
    scan_offsets_kernel<<<1, 64>>>();
    scan_local_kernel<<<NSCAN, SCAN_BLK>>>();
    fill_kernel<<<(E_EDGES + 255) / 256, 256>>>();

    gat_node_kernel<<<(N_NODES + 7) / 8, 256>>>(bias, out);
}

// round 5
// speedup vs baseline: 2.3163x; 1.2297x over previous
#include <cuda_runtime.h>
#include <cuda_fp16.h>
#include <math_constants.h>
#include <cstdint>

#define N_NODES 50000
#define E_EDGES 800000
#define HEADS 4
#define IN_DIM 256
#define HC 256
#define NEG_SLOPE 0.2f

// ---------------- device scratch ----------------
__device__ __half g_hh[N_NODES * HC];        // x @ W in fp16 (25.6 MB)
__device__ float g_wt[IN_DIM * HC];          // W transposed: [n][k]
__device__ float g_asrc[N_NODES * HEADS];
__device__ float g_adst[N_NODES * HEADS];
__device__ int   g_src[E_EDGES];
__device__ int   g_dst[E_EDGES];
__device__ int   g_deg[N_NODES];
__device__ int   g_rowstart[N_NODES + 1];
__device__ int   g_cursor[N_NODES];
__device__ int   g_csr[E_EDGES];
__device__ int   g_is64;
#define SCAN_BLK 1024
#define NSCAN ((N_NODES + SCAN_BLK - 1) / SCAN_BLK)   // 49
__device__ int   g_bsum[NSCAN];
__device__ int   g_boff[NSCAN];

// ---------------- dtype detection ----------------
__global__ void detect_kernel(const unsigned int* __restrict__ w) {
    __shared__ unsigned int r[256];
    unsigned int acc = 0;
    for (int i = threadIdx.x; i < 8192; i += 256) acc |= w[2 * i + 1];
    r[threadIdx.x] = acc;
    __syncthreads();
    if (threadIdx.x == 0) {
        unsigned int a = 0;
        #pragma unroll 8
        for (int i = 0; i < 256; i++) a |= r[i];
        g_is64 = (a == 0u) ? 1 : 0;
    }
}

__global__ void zero_deg_kernel() {
    int i = blockIdx.x * blockDim.x + threadIdx.x;
    if (i < N_NODES) g_deg[i] = 0;
}

__global__ void convert_kernel(const void* __restrict__ ei) {
    int e = blockIdx.x * blockDim.x + threadIdx.x;
    if (e >= E_EDGES) return;
    int s, d;
    if (g_is64) {
        const long long* p = (const long long*)ei;
        s = (int)p[e];
        d = (int)p[E_EDGES + e];
    } else {
        const int* p = (const int*)ei;
        s = p[e];
        d = p[E_EDGES + e];
    }
    g_src[e] = s;
    g_dst[e] = d;
    atomicAdd(&g_deg[d], 1);
}

// ---------------- W transpose (256x256) ----------------
__global__ void transpose_w_kernel(const float* __restrict__ W) {
    __shared__ float t[32][33];
    const int bx = blockIdx.x * 32, by = blockIdx.y * 32;
    #pragma unroll
    for (int i = 0; i < 4; i++)
        t[threadIdx.y + i * 8][threadIdx.x] = W[(by + threadIdx.y + i * 8) * HC + bx + threadIdx.x];
    __syncthreads();
    #pragma unroll
    for (int i = 0; i < 4; i++)
        g_wt[(bx + threadIdx.y + i * 8) * IN_DIM + by + threadIdx.x] = t[threadIdx.x][threadIdx.y + i * 8];
}

// ---------------- TF32 GEMM 128x128, ldmatrix fragments ----------------
#define GBM 128
#define GBN 128
#define GBK 16
#define TILE_FLOATS (128 * 16)

__device__ __forceinline__ float to_tf32(float x) {
    unsigned int r;
    asm("cvt.rna.tf32.f32 %0, %1;" : "=r"(r) : "f"(x));
    return __uint_as_float(r);
}

__device__ __forceinline__ void ldsm_x4(uint32_t addr, uint32_t& r0, uint32_t& r1,
                                        uint32_t& r2, uint32_t& r3) {
    asm volatile("ldmatrix.sync.aligned.m8n8.x4.shared.b16 {%0,%1,%2,%3}, [%4];"
                 : "=r"(r0), "=r"(r1), "=r"(r2), "=r"(r3) : "r"(addr));
}

__device__ __forceinline__ void mma_tf32(float4& d, const uint32_t* a, const uint32_t* b) {
    asm volatile(
        "mma.sync.aligned.m16n8k8.row.col.f32.tf32.tf32.f32 "
        "{%0,%1,%2,%3}, {%4,%5,%6,%7}, {%8,%9}, {%0,%1,%2,%3};\n"
        : "+f"(d.x), "+f"(d.y), "+f"(d.z), "+f"(d.w)
        : "r"(a[0]), "r"(a[1]), "r"(a[2]), "r"(a[3]),
          "r"(b[0]), "r"(b[1]));
}

__global__ __launch_bounds__(256, 2) void sgemm_tf32_kernel(
    const float* __restrict__ x,
    const float* __restrict__ att_src, const float* __restrict__ att_dst) {
    __shared__ __align__(16) float As[2][TILE_FLOATS];
    __shared__ __align__(16) float Bs[2][TILE_FLOATS];

    const int tid  = threadIdx.x;
    const int w    = tid >> 5;
    const int lane = tid & 31;
    const int gid  = lane >> 2;
    const int tig  = lane & 3;
    const int wm   = w & 3;
    const int wn   = w >> 2;
    const int rowblk = blockIdx.y * GBM;
    const int col0   = blockIdx.x * GBN;

    float4 acc[2][8];
    #pragma unroll
    for (int i = 0; i < 2; i++)
        #pragma unroll
        for (int j = 0; j < 8; j++) acc[i][j] = make_float4(0.f, 0.f, 0.f, 0.f);

    const int l_row = tid >> 1;
    const int l_kc  = (tid & 1) * 8;
    int a_grow = rowblk + l_row;
    if (a_grow > N_NODES - 1) a_grow = N_NODES - 1;
    const int b_grow = col0 + l_row;

    const int swq   = (l_row >> 1) & 3;
    const int c0    = (tid & 1) * 2;
    const int sts0  = l_row * 16 + ((c0 ^ swq) << 2);
    const int sts1  = l_row * 16 + (((c0 + 1) ^ swq) << 2);

    const int lr  = (lane & 7) | (lane & 8);
    const int csl = lane >> 4;
    const int q2  = (lr >> 1) & 3;
    const uint32_t loff0 = lr * 64 + (((0 + csl) ^ q2) << 4);
    const uint32_t loff1 = lr * 64 + (((2 + csl) ^ q2) << 4);

    const uint32_t aB0 = (uint32_t)__cvta_generic_to_shared(&As[0][0]);
    const uint32_t aB1 = (uint32_t)__cvta_generic_to_shared(&As[1][0]);
    const uint32_t bB0 = (uint32_t)__cvta_generic_to_shared(&Bs[0][0]);
    const uint32_t bB1 = (uint32_t)__cvta_generic_to_shared(&Bs[1][0]);

    float4 ar0, ar1, br0, br1;
    auto ldgA = [&](int k0) {
        const float* p = &x[(size_t)a_grow * IN_DIM + k0 + l_kc];
        ar0 = *(const float4*)p;
        ar1 = *(const float4*)(p + 4);
    };
    auto ldgB = [&](int k0) {
        const float* p = &g_wt[(size_t)b_grow * IN_DIM + k0 + l_kc];
        br0 = *(const float4*)p;
        br1 = *(const float4*)(p + 4);
    };
    auto stsA = [&](int buf) {
        float* d = As[buf];
        *(float4*)&d[sts0] = make_float4(to_tf32(ar0.x), to_tf32(ar0.y), to_tf32(ar0.z), to_tf32(ar0.w));
        *(float4*)&d[sts1] = make_float4(to_tf32(ar1.x), to_tf32(ar1.y), to_tf32(ar1.z), to_tf32(ar1.w));
    };
    auto stsB = [&](int buf) {
        float* d = Bs[buf];
        *(float4*)&d[sts0] = make_float4(to_tf32(br0.x), to_tf32(br0.y), to_tf32(br0.z), to_tf32(br0.w));
        *(float4*)&d[sts1] = make_float4(to_tf32(br1.x), to_tf32(br1.y), to_tf32(br1.z), to_tf32(br1.w));
    };

    auto compute = [&](int buf) {
        const uint32_t Ab = buf ? aB1 : aB0;
        const uint32_t Bb = buf ? bB1 : bB0;
        #pragma unroll
        for (int kbi = 0; kbi < 2; kbi++) {
            const uint32_t lo = kbi ? loff1 : loff0;
            uint32_t afr[2][4], bfr[8][2];
            #pragma unroll
            for (int mt = 0; mt < 2; mt++) {
                uint32_t addr = Ab + (uint32_t)((wm * 32 + mt * 16) * 64) + lo;
                ldsm_x4(addr, afr[mt][0], afr[mt][1], afr[mt][2], afr[mt][3]);
            }
            #pragma unroll
            for (int ntp = 0; ntp < 4; ntp++) {
                uint32_t addr = Bb + (uint32_t)((wn * 64 + ntp * 16) * 64) + lo;
                ldsm_x4(addr, bfr[2 * ntp][0], bfr[2 * ntp + 1][0],
                              bfr[2 * ntp][1], bfr[2 * ntp + 1][1]);
            }
            #pragma unroll
            for (int mt = 0; mt < 2; mt++)
                #pragma unroll
                for (int nt = 0; nt < 8; nt++)
                    mma_tf32(acc[mt][nt], afr[mt], bfr[nt]);
        }
    };

    ldgA(0); ldgB(0);
    stsA(0); stsB(0);
    ldgA(GBK); ldgB(GBK);
    __syncthreads();

    const int NIT = IN_DIM / GBK;
    for (int it = 0; it < NIT; ++it) {
        if (it + 1 < NIT) { stsA((it + 1) & 1); stsB((it + 1) & 1); }
        if (it + 2 < NIT) { ldgA((it + 2) * GBK); ldgB((it + 2) * GBK); }
        compute(it & 1);
        __syncthreads();
    }

    // epilogue: store h (fp16) + fused attention dots (warp cols = one head)
    const int head = blockIdx.x * 2 + wn;
    float2 avs[8], avd[8];
    #pragma unroll
    for (int nt = 0; nt < 8; nt++) {
        int c = col0 + wn * 64 + nt * 8 + tig * 2;
        avs[nt] = *(const float2*)&att_src[c];
        avd[nt] = *(const float2*)&att_dst[c];
    }

    #pragma unroll
    for (int mt = 0; mt < 2; mt++) {
        int row0 = rowblk + wm * 32 + mt * 16 + gid;
        int row1 = row0 + 8;
        float s0 = 0.f, s1 = 0.f, t0 = 0.f, t1 = 0.f;
        #pragma unroll
        for (int nt = 0; nt < 8; nt++) {
            float4 d = acc[mt][nt];
            int col = col0 + wn * 64 + nt * 8 + tig * 2;
            if (row0 < N_NODES)
                *(__half2*)&g_hh[(size_t)row0 * HC + col] = __floats2half2_rn(d.x, d.y);
            if (row1 < N_NODES)
                *(__half2*)&g_hh[(size_t)row1 * HC + col] = __floats2half2_rn(d.z, d.w);
            s0 += d.x * avs[nt].x + d.y * avs[nt].y;
            s1 += d.z * avs[nt].x + d.w * avs[nt].y;
            t0 += d.x * avd[nt].x + d.y * avd[nt].y;
            t1 += d.z * avd[nt].x + d.w * avd[nt].y;
        }
        #pragma unroll
        for (int off = 1; off <= 2; off <<= 1) {
            s0 += __shfl_xor_sync(0xffffffffu, s0, off);
            s1 += __shfl_xor_sync(0xffffffffu, s1, off);
            t0 += __shfl_xor_sync(0xffffffffu, t0, off);
            t1 += __shfl_xor_sync(0xffffffffu, t1, off);
        }
        if (tig == 0) {
            if (row0 < N_NODES) { g_asrc[row0 * HEADS + head] = s0; g_adst[row0 * HEADS + head] = t0; }
            if (row1 < N_NODES) { g_asrc[row1 * HEADS + head] = s1; g_adst[row1 * HEADS + head] = t1; }
        }
    }
}

// ---------------- multi-block scan ----------------
__global__ void scan_reduce_kernel() {
    __shared__ int ws[32];
    int i = blockIdx.x * SCAN_BLK + threadIdx.x;
    int v = (i < N_NODES) ? g_deg[i] : 0;
    #pragma unroll
    for (int off = 16; off; off >>= 1) v += __shfl_xor_sync(0xffffffffu, v, off);
    if ((threadIdx.x & 31) == 0) ws[threadIdx.x >> 5] = v;
    __syncthreads();
    if (threadIdx.x < 32) {
        int t = ws[threadIdx.x];
        #pragma unroll
        for (int off = 16; off; off >>= 1) t += __shfl_xor_sync(0xffffffffu, t, off);
        if (threadIdx.x == 0) g_bsum[blockIdx.x] = t;
    }
}

__global__ void scan_offsets_kernel() {
    __shared__ int tmp[64];
    int t = threadIdx.x;
    int v = (t < NSCAN) ? g_bsum[t] : 0;
    tmp[t] = v;
    __syncthreads();
    #pragma unroll
    for (int off = 1; off < 64; off <<= 1) {
        int a = (t >= off) ? tmp[t - off] : 0;
        __syncthreads();
        tmp[t] += a;
        __syncthreads();
    }
    if (t < NSCAN) g_boff[t] = tmp[t] - v;
    if (t == NSCAN - 1) g_rowstart[N_NODES] = tmp[t];
}

__global__ void scan_local_kernel() {
    __shared__ int wsums[32];
    const int tid = threadIdx.x, wid = tid >> 5, lane = tid & 31;
    int i = blockIdx.x * SCAN_BLK + tid;
    int v = (i < N_NODES) ? g_deg[i] : 0;
    int incl = v;
    #pragma unroll
    for (int off = 1; off < 32; off <<= 1) {
        int t = __shfl_up_sync(0xffffffffu, incl, off);
        if (lane >= off) incl += t;
    }
    if (lane == 31) wsums[wid] = incl;
    __syncthreads();
    if (wid == 0) {
        int wv = wsums[lane];
        #pragma unroll
        for (int off = 1; off < 32; off <<= 1) {
            int t = __shfl_up_sync(0xffffffffu, wv, off);
            if (lane >= off) wv += t;
        }
        wsums[lane] = wv;
    }
    __syncthreads();
    if (i < N_NODES) {
        int start = g_boff[blockIdx.x] + ((wid > 0) ? wsums[wid - 1] : 0) + incl - v;
        g_rowstart[i] = start;
        g_cursor[i]   = start;
    }
}

__global__ void fill_kernel() {
    int e = blockIdx.x * blockDim.x + threadIdx.x;
    if (e < E_EDGES) {
        int d = g_dst[e];
        int slot = atomicAdd(&g_cursor[d], 1);
        g_csr[slot] = g_src[e];
    }
}

// ---------------- fused softmax + gather + bias + relu (fp16 features) ----------------
#define CAP 96
__device__ __forceinline__ void h8_accum(const __half* p, float a, float* acc) {
    uint4 v = *(const uint4*)p;
    float2 f0 = __half22float2(*(const __half2*)&v.x);
    float2 f1 = __half22float2(*(const __half2*)&v.y);
    float2 f2 = __half22float2(*(const __half2*)&v.z);
    float2 f3 = __half22float2(*(const __half2*)&v.w);
    acc[0] += a * f0.x; acc[1] += a * f0.y;
    acc[2] += a * f1.x; acc[3] += a * f1.y;
    acc[4] += a * f2.x; acc[5] += a * f2.y;
    acc[6] += a * f3.x; acc[7] += a * f3.y;
}

__global__ __launch_bounds__(256) void gat_node_kernel(const float* __restrict__ bias,
                                                       float* __restrict__ out) {
    __shared__ float s_lg[8][CAP][4];
    __shared__ int   s_src[8][CAP];

    const int w    = threadIdx.x >> 5;
    const int lane = threadIdx.x & 31;
    const int node = (blockIdx.x * blockDim.x + threadIdx.x) >> 5;
    if (node >= N_NODES) return;
    const int n   = node;
    const int rs  = g_rowstart[n];
    const int deg = g_rowstart[n + 1] - rs;
    const int tot = deg + 1;

    float4 ad4 = *(const float4*)&g_adst[n * HEADS];
    float ad[4] = {ad4.x, ad4.y, ad4.z, ad4.w};
    const int myh = lane >> 3;

    float acc[8] = {0.f, 0.f, 0.f, 0.f, 0.f, 0.f, 0.f, 0.f};

    if (tot <= CAP) {
        float m[4] = {-CUDART_INF_F, -CUDART_INF_F, -CUDART_INF_F, -CUDART_INF_F};
        for (int i = lane; i < tot; i += 32) {
            int src = (i < deg) ? g_csr[rs + i] : n;
            s_src[w][i] = src;
            float4 a4 = *(const float4*)&g_asrc[src * HEADS];
            float lg[4] = {a4.x + ad[0], a4.y + ad[1], a4.z + ad[2], a4.w + ad[3]};
            #pragma unroll
            for (int h = 0; h < 4; h++) {
                lg[h] = lg[h] >= 0.f ? lg[h] : NEG_SLOPE * lg[h];
                m[h] = fmaxf(m[h], lg[h]);
            }
            *(float4*)&s_lg[w][i][0] = make_float4(lg[0], lg[1], lg[2], lg[3]);
        }
        #pragma unroll
        for (int off = 16; off; off >>= 1)
            #pragma unroll
            for (int h = 0; h < 4; h++)
                m[h] = fmaxf(m[h], __shfl_xor_sync(0xffffffffu, m[h], off));

        float s[4] = {0.f, 0.f, 0.f, 0.f};
        for (int i = lane; i < tot; i += 32) {
            float4 L = *(const float4*)&s_lg[w][i][0];
            float e0 = __expf(L.x - m[0]);
            float e1 = __expf(L.y - m[1]);
            float e2 = __expf(L.z - m[2]);
            float e3 = __expf(L.w - m[3]);
            s[0] += e0; s[1] += e1; s[2] += e2; s[3] += e3;
            *(float4*)&s_lg[w][i][0] = make_float4(e0, e1, e2, e3);
        }
        #pragma unroll
        for (int off = 16; off; off >>= 1)
            #pragma unroll
            for (int h = 0; h < 4; h++)
                s[h] += __shfl_xor_sync(0xffffffffu, s[h], off);

        const float inv = 1.f / (s[myh] + 1e-16f);
        __syncwarp();

        int i = 0;
        for (; i + 4 <= tot; i += 4) {
            int   sA = s_src[w][i],     sB = s_src[w][i + 1];
            int   sC = s_src[w][i + 2], sD = s_src[w][i + 3];
            float aA = s_lg[w][i][myh] * inv,     aB = s_lg[w][i + 1][myh] * inv;
            float aC = s_lg[w][i + 2][myh] * inv, aD = s_lg[w][i + 3][myh] * inv;
            const __half* pA = &g_hh[(size_t)sA * HC + lane * 8];
            const __half* pB = &g_hh[(size_t)sB * HC + lane * 8];
            const __half* pC = &g_hh[(size_t)sC * HC + lane * 8];
            const __half* pD = &g_hh[(size_t)sD * HC + lane * 8];
            h8_accum(pA, aA, acc);
            h8_accum(pB, aB, acc);
            h8_accum(pC, aC, acc);
            h8_accum(pD, aD, acc);
        }
        for (; i < tot; i++) {
            int   s0 = s_src[w][i];
            float a0 = s_lg[w][i][myh] * inv;
            h8_accum(&g_hh[(size_t)s0 * HC + lane * 8], a0, acc);
        }
    } else {
        float m[4] = {-CUDART_INF_F, -CUDART_INF_F, -CUDART_INF_F, -CUDART_INF_F};
        for (int i = lane; i < tot; i += 32) {
            int src = (i < deg) ? g_csr[rs + i] : n;
            float4 a4 = *(const float4*)&g_asrc[src * HEADS];
            float lg[4] = {a4.x + ad[0], a4.y + ad[1], a4.z + ad[2], a4.w + ad[3]};
            #pragma unroll
            for (int h = 0; h < 4; h++) {
                float v = lg[h] >= 0.f ? lg[h] : NEG_SLOPE * lg[h];
                m[h] = fmaxf(m[h], v);
            }
        }
        #pragma unroll
        for (int off = 16; off; off >>= 1)
            #pragma unroll
            for (int h = 0; h < 4; h++)
                m[h] = fmaxf(m[h], __shfl_xor_sync(0xffffffffu, m[h], off));

        float s[4] = {0.f, 0.f, 0.f, 0.f};
        for (int i = lane; i < tot; i += 32) {
            int src = (i < deg) ? g_csr[rs + i] : n;
            float4 a4 = *(const float4*)&g_asrc[src * HEADS];
            float lg[4] = {a4.x + ad[0], a4.y + ad[1], a4.z + ad[2], a4.w + ad[3]};
            #pragma unroll
            for (int h = 0; h < 4; h++) {
                float v = lg[h] >= 0.f ? lg[h] : NEG_SLOPE * lg[h];
                s[h] += __expf(v - m[h]);
            }
        }
        #pragma unroll
        for (int off = 16; off; off >>= 1)
            #pragma unroll
            for (int h = 0; h < 4; h++)
                s[h] += __shfl_xor_sync(0xffffffffu, s[h], off);

        const float mh  = m[myh];
        const float inv = 1.f / (s[myh] + 1e-16f);
        const float adh = ad[myh];
        for (int i = 0; i < tot; i++) {
            int src = (i < deg) ? g_csr[rs + i] : n;
            float av = g_asrc[src * HEADS + myh];
            float lg = av + adh;
            lg = lg >= 0.f ? lg : NEG_SLOPE * lg;
            float alpha = __expf(lg - mh) * inv;
            h8_accum(&g_hh[(size_t)src * HC + lane * 8], alpha, acc);
        }
    }

    float4 b0 = ((const float4*)bias)[lane * 2];
    float4 b1 = ((const float4*)bias)[lane * 2 + 1];
    float4 o0, o1;
    o0.x = fmaxf(acc[0] + b0.x, 0.f); o0.y = fmaxf(acc[1] + b0.y, 0.f);
    o0.z = fmaxf(acc[2] + b0.z, 0.f); o0.w = fmaxf(acc[3] + b0.w, 0.f);
    o1.x = fmaxf(acc[4] + b1.x, 0.f); o1.y = fmaxf(acc[5] + b1.y, 0.f);
    o1.z = fmaxf(acc[6] + b1.z, 0.f); o1.w = fmaxf(acc[7] + b1.w, 0.f);
    *(float4*)&out[(size_t)n * HC + lane * 8]     = o0;
    *(float4*)&out[(size_t)n * HC + lane * 8 + 4] = o1;
}

// ---------------- launch ----------------
extern "C" void kernel_launch(void* const* d_in, const int* in_sizes, int n_in,
                              void* d_out, int out_size) {
    const float* x       = (const float*)d_in[0];
    const void*  ei      = d_in[1];
    const float* W       = (const float*)d_in[2];
    const float* att_src = (const float*)d_in[3];
    const float* att_dst = (const float*)d_in[4];
    const float* bias    = (const float*)d_in[5];
    float*       out     = (float*)d_out;

    detect_kernel<<<1, 256>>>((const unsigned int*)ei);
    zero_deg_kernel<<<(N_NODES + 255) / 256, 256>>>();
    convert_kernel<<<(E_EDGES + 255) / 256, 256>>>(ei);

    dim3 tg(8, 8);
    transpose_w_kernel<<<tg, dim3(32, 8)>>>(W);

    dim3 gg(HC / GBN, (N_NODES + GBM - 1) / GBM);   // (2, 391)
    sgemm_tf32_kernel<<<gg, 256>>>(x, att_src, att_dst);

    scan_reduce_kernel<<<NSCAN, SCAN_BLK>>>();
    scan_offsets_kernel<<<1, 64>>>();
    scan_local_kernel<<<NSCAN, SCAN_BLK>>>();
    fill_kernel<<<(E_EDGES + 255) / 256, 256>>>();

    gat_node_kernel<<<(N_NODES + 7) / 8, 256>>>(bias, out);
}

// round 6
// speedup vs baseline: 2.8062x; 1.2115x over previous
#include <cuda_runtime.h>
#include <cuda_fp16.h>
#include <math_constants.h>
#include <cstdint>

#define N_NODES 50000
#define E_EDGES 800000
#define HEADS 4
#define IN_DIM 256
#define HC 256
#define NEG_SLOPE 0.2f

// ---------------- device scratch ----------------
__device__ __half g_hh[N_NODES * HC];        // x @ W in fp16 (25.6 MB)
__device__ __half g_wth[IN_DIM * HC];        // W transposed + fp16: [n][k]
__device__ float g_asrc[N_NODES * HEADS];
__device__ float g_adst[N_NODES * HEADS];
__device__ int   g_src[E_EDGES];
__device__ int   g_dst[E_EDGES];
__device__ int   g_deg[N_NODES];
__device__ int   g_rowstart[N_NODES + 1];
__device__ int   g_cursor[N_NODES];
__device__ int   g_csr[E_EDGES];
__device__ int   g_is64;
#define SCAN_BLK 1024
#define NSCAN ((N_NODES + SCAN_BLK - 1) / SCAN_BLK)   // 49
__device__ int   g_bsum[NSCAN];
__device__ int   g_boff[NSCAN];

// ---------------- dtype detection ----------------
__global__ void detect_kernel(const unsigned int* __restrict__ w) {
    __shared__ unsigned int r[256];
    unsigned int acc = 0;
    for (int i = threadIdx.x; i < 8192; i += 256) acc |= w[2 * i + 1];
    r[threadIdx.x] = acc;
    __syncthreads();
    if (threadIdx.x == 0) {
        unsigned int a = 0;
        #pragma unroll 8
        for (int i = 0; i < 256; i++) a |= r[i];
        g_is64 = (a == 0u) ? 1 : 0;
    }
}

__global__ void zero_deg_kernel() {
    int i = blockIdx.x * blockDim.x + threadIdx.x;
    if (i < N_NODES) g_deg[i] = 0;
}

__global__ void convert_kernel(const void* __restrict__ ei) {
    int e = blockIdx.x * blockDim.x + threadIdx.x;
    if (e >= E_EDGES) return;
    int s, d;
    if (g_is64) {
        const long long* p = (const long long*)ei;
        s = (int)p[e];
        d = (int)p[E_EDGES + e];
    } else {
        const int* p = (const int*)ei;
        s = p[e];
        d = p[E_EDGES + e];
    }
    g_src[e] = s;
    g_dst[e] = d;
    atomicAdd(&g_deg[d], 1);
}

// ---------------- W transpose + fp16 convert (256x256) ----------------
__global__ void transpose_w_kernel(const float* __restrict__ W) {
    __shared__ float t[32][33];
    const int bx = blockIdx.x * 32, by = blockIdx.y * 32;
    #pragma unroll
    for (int i = 0; i < 4; i++)
        t[threadIdx.y + i * 8][threadIdx.x] = W[(by + threadIdx.y + i * 8) * HC + bx + threadIdx.x];
    __syncthreads();
    #pragma unroll
    for (int i = 0; i < 4; i++)
        g_wth[(bx + threadIdx.y + i * 8) * IN_DIM + by + threadIdx.x] =
            __float2half_rn(t[threadIdx.x][threadIdx.y + i * 8]);
}

// ---------------- FP16 GEMM 128x128, BK=32, ldmatrix + m16n8k16 ----------------
#define GBM 128
#define GBN 128
#define GBK 32
#define TILE_HALVES (128 * 32)   // 8192 B per buffer

__device__ __forceinline__ void ldsm_x4(uint32_t addr, uint32_t& r0, uint32_t& r1,
                                        uint32_t& r2, uint32_t& r3) {
    asm volatile("ldmatrix.sync.aligned.m8n8.x4.shared.b16 {%0,%1,%2,%3}, [%4];"
                 : "=r"(r0), "=r"(r1), "=r"(r2), "=r"(r3) : "r"(addr));
}

__device__ __forceinline__ void mma_f16(float4& d, const uint32_t* a, const uint32_t* b) {
    asm volatile(
        "mma.sync.aligned.m16n8k16.row.col.f32.f16.f16.f32 "
        "{%0,%1,%2,%3}, {%4,%5,%6,%7}, {%8,%9}, {%0,%1,%2,%3};\n"
        : "+f"(d.x), "+f"(d.y), "+f"(d.z), "+f"(d.w)
        : "r"(a[0]), "r"(a[1]), "r"(a[2]), "r"(a[3]),
          "r"(b[0]), "r"(b[1]));
}

__global__ __launch_bounds__(256, 2) void hgemm_kernel(
    const float* __restrict__ x,
    const float* __restrict__ att_src, const float* __restrict__ att_dst) {
    __shared__ __align__(16) __half As[2][TILE_HALVES];
    __shared__ __align__(16) __half Bs[2][TILE_HALVES];

    const int tid  = threadIdx.x;
    const int w    = tid >> 5;
    const int lane = tid & 31;
    const int gid  = lane >> 2;
    const int tig  = lane & 3;
    const int wm   = w & 3;    // 4 row groups of 32
    const int wn   = w >> 2;   // 2 col groups of 64
    const int rowblk = blockIdx.y * GBM;
    const int col0   = blockIdx.x * GBN;

    float4 acc[2][8];
    #pragma unroll
    for (int i = 0; i < 2; i++)
        #pragma unroll
        for (int j = 0; j < 8; j++) acc[i][j] = make_float4(0.f, 0.f, 0.f, 0.f);

    // loader: row = tid>>1 (0..127); (tid&1) selects k range [hs*16, hs*16+16)
    const int l_row = tid >> 1;
    const int hs    = tid & 1;
    int a_grow = rowblk + l_row;
    if (a_grow > N_NODES - 1) a_grow = N_NODES - 1;
    const int b_grow = col0 + l_row;

    // STS: two 8-half chunks c0, c0+1 with chunk-XOR swizzle (rows = 32 halves = 64B)
    const int swq  = (l_row >> 1) & 3;
    const int c0   = hs * 2;
    const int sts0 = l_row * 32 + ((c0 ^ swq) << 3);       // in halves
    const int sts1 = l_row * 32 + (((c0 + 1) ^ swq) << 3);

    // ldmatrix lane offsets (bytes): 64B rows, 4 chunks of 16B
    const int lr  = lane & 15;
    const int csl = lane >> 4;
    const int q2  = (lr >> 1) & 3;
    const uint32_t loff0 = lr * 64 + (((0 + csl) ^ q2) << 4);  // k-step 0 (chunks 0,1)
    const uint32_t loff1 = lr * 64 + (((2 + csl) ^ q2) << 4);  // k-step 1 (chunks 2,3)

    const uint32_t aB0 = (uint32_t)__cvta_generic_to_shared(&As[0][0]);
    const uint32_t aB1 = (uint32_t)__cvta_generic_to_shared(&As[1][0]);
    const uint32_t bB0 = (uint32_t)__cvta_generic_to_shared(&Bs[0][0]);
    const uint32_t bB1 = (uint32_t)__cvta_generic_to_shared(&Bs[1][0]);

    float4 ar0, ar1, ar2, ar3;   // 16 x floats
    uint4  br0, br1;             // 16 W halves
    auto ldgA = [&](int k0) {
        const float* p = &x[(size_t)a_grow * IN_DIM + k0 + hs * 16];
        ar0 = *(const float4*)p;
        ar1 = *(const float4*)(p + 4);
        ar2 = *(const float4*)(p + 8);
        ar3 = *(const float4*)(p + 12);
    };
    auto ldgB = [&](int k0) {
        const uint4* p = (const uint4*)&g_wth[(size_t)b_grow * IN_DIM + k0 + hs * 16];
        br0 = p[0];
        br1 = p[1];
    };
    auto stsA = [&](int buf) {
        __half* d = As[buf];
        __align__(16) __half2 t0[4], t1[4];
        t0[0] = __floats2half2_rn(ar0.x, ar0.y);
        t0[1] = __floats2half2_rn(ar0.z, ar0.w);
        t0[2] = __floats2half2_rn(ar1.x, ar1.y);
        t0[3] = __floats2half2_rn(ar1.z, ar1.w);
        t1[0] = __floats2half2_rn(ar2.x, ar2.y);
        t1[1] = __floats2half2_rn(ar2.z, ar2.w);
        t1[2] = __floats2half2_rn(ar3.x, ar3.y);
        t1[3] = __floats2half2_rn(ar3.z, ar3.w);
        *(uint4*)&d[sts0] = *(const uint4*)t0;
        *(uint4*)&d[sts1] = *(const uint4*)t1;
    };
    auto stsB = [&](int buf) {
        __half* d = Bs[buf];
        *(uint4*)&d[sts0] = br0;
        *(uint4*)&d[sts1] = br1;
    };

    auto compute = [&](int buf) {
        const uint32_t Ab = buf ? aB1 : aB0;
        const uint32_t Bb = buf ? bB1 : bB0;
        #pragma unroll
        for (int kbi = 0; kbi < 2; kbi++) {
            const uint32_t lo = kbi ? loff1 : loff0;
            uint32_t afr[2][4], bfr[8][2];
            #pragma unroll
            for (int mt = 0; mt < 2; mt++) {
                uint32_t addr = Ab + (uint32_t)((wm * 32 + mt * 16) * 64) + lo;
                ldsm_x4(addr, afr[mt][0], afr[mt][1], afr[mt][2], afr[mt][3]);
            }
            #pragma unroll
            for (int ntp = 0; ntp < 4; ntp++) {
                uint32_t addr = Bb + (uint32_t)((wn * 64 + ntp * 16) * 64) + lo;
                ldsm_x4(addr, bfr[2 * ntp][0], bfr[2 * ntp + 1][0],
                              bfr[2 * ntp][1], bfr[2 * ntp + 1][1]);
            }
            #pragma unroll
            for (int mt = 0; mt < 2; mt++)
                #pragma unroll
                for (int nt = 0; nt < 8; nt++)
                    mma_f16(acc[mt][nt], afr[mt], bfr[nt]);
        }
    };

    ldgA(0); ldgB(0);
    stsA(0); stsB(0);
    ldgA(GBK); ldgB(GBK);
    __syncthreads();

    const int NIT = IN_DIM / GBK;   // 8
    for (int it = 0; it < NIT; ++it) {
        if (it + 1 < NIT) { stsA((it + 1) & 1); stsB((it + 1) & 1); }
        if (it + 2 < NIT) { ldgA((it + 2) * GBK); ldgB((it + 2) * GBK); }
        compute(it & 1);
        __syncthreads();
    }

    // epilogue: store h (fp16) + fused attention dots (warp cols = one head)
    const int head = blockIdx.x * 2 + wn;
    float2 avs[8], avd[8];
    #pragma unroll
    for (int nt = 0; nt < 8; nt++) {
        int c = col0 + wn * 64 + nt * 8 + tig * 2;
        avs[nt] = *(const float2*)&att_src[c];
        avd[nt] = *(const float2*)&att_dst[c];
    }

    #pragma unroll
    for (int mt = 0; mt < 2; mt++) {
        int row0 = rowblk + wm * 32 + mt * 16 + gid;
        int row1 = row0 + 8;
        float s0 = 0.f, s1 = 0.f, t0 = 0.f, t1 = 0.f;
        #pragma unroll
        for (int nt = 0; nt < 8; nt++) {
            float4 d = acc[mt][nt];
            int col = col0 + wn * 64 + nt * 8 + tig * 2;
            if (row0 < N_NODES)
                *(__half2*)&g_hh[(size_t)row0 * HC + col] = __floats2half2_rn(d.x, d.y);
            if (row1 < N_NODES)
                *(__half2*)&g_hh[(size_t)row1 * HC + col] = __floats2half2_rn(d.z, d.w);
            s0 += d.x * avs[nt].x + d.y * avs[nt].y;
            s1 += d.z * avs[nt].x + d.w * avs[nt].y;
            t0 += d.x * avd[nt].x + d.y * avd[nt].y;
            t1 += d.z * avd[nt].x + d.w * avd[nt].y;
        }
        #pragma unroll
        for (int off = 1; off <= 2; off <<= 1) {
            s0 += __shfl_xor_sync(0xffffffffu, s0, off);
            s1 += __shfl_xor_sync(0xffffffffu, s1, off);
            t0 += __shfl_xor_sync(0xffffffffu, t0, off);
            t1 += __shfl_xor_sync(0xffffffffu, t1, off);
        }
        if (tig == 0) {
            if (row0 < N_NODES) { g_asrc[row0 * HEADS + head] = s0; g_adst[row0 * HEADS + head] = t0; }
            if (row1 < N_NODES) { g_asrc[row1 * HEADS + head] = s1; g_adst[row1 * HEADS + head] = t1; }
        }
    }
}

// ---------------- multi-block scan ----------------
__global__ void scan_reduce_kernel() {
    __shared__ int ws[32];
    int i = blockIdx.x * SCAN_BLK + threadIdx.x;
    int v = (i < N_NODES) ? g_deg[i] : 0;
    #pragma unroll
    for (int off = 16; off; off >>= 1) v += __shfl_xor_sync(0xffffffffu, v, off);
    if ((threadIdx.x & 31) == 0) ws[threadIdx.x >> 5] = v;
    __syncthreads();
    if (threadIdx.x < 32) {
        int t = ws[threadIdx.x];
        #pragma unroll
        for (int off = 16; off; off >>= 1) t += __shfl_xor_sync(0xffffffffu, t, off);
        if (threadIdx.x == 0) g_bsum[blockIdx.x] = t;
    }
}

__global__ void scan_offsets_kernel() {
    __shared__ int tmp[64];
    int t = threadIdx.x;
    int v = (t < NSCAN) ? g_bsum[t] : 0;
    tmp[t] = v;
    __syncthreads();
    #pragma unroll
    for (int off = 1; off < 64; off <<= 1) {
        int a = (t >= off) ? tmp[t - off] : 0;
        __syncthreads();
        tmp[t] += a;
        __syncthreads();
    }
    if (t < NSCAN) g_boff[t] = tmp[t] - v;
    if (t == NSCAN - 1) g_rowstart[N_NODES] = tmp[t];
}

__global__ void scan_local_kernel() {
    __shared__ int wsums[32];
    const int tid = threadIdx.x, wid = tid >> 5, lane = tid & 31;
    int i = blockIdx.x * SCAN_BLK + tid;
    int v = (i < N_NODES) ? g_deg[i] : 0;
    int incl = v;
    #pragma unroll
    for (int off = 1; off < 32; off <<= 1) {
        int t = __shfl_up_sync(0xffffffffu, incl, off);
        if (lane >= off) incl += t;
    }
    if (lane == 31) wsums[wid] = incl;
    __syncthreads();
    if (wid == 0) {
        int wv = wsums[lane];
        #pragma unroll
        for (int off = 1; off < 32; off <<= 1) {
            int t = __shfl_up_sync(0xffffffffu, wv, off);
            if (lane >= off) wv += t;
        }
        wsums[lane] = wv;
    }
    __syncthreads();
    if (i < N_NODES) {
        int start = g_boff[blockIdx.x] + ((wid > 0) ? wsums[wid - 1] : 0) + incl - v;
        g_rowstart[i] = start;
        g_cursor[i]   = start;
    }
}

__global__ void fill_kernel() {
    int e = blockIdx.x * blockDim.x + threadIdx.x;
    if (e < E_EDGES) {
        int d = g_dst[e];
        int slot = atomicAdd(&g_cursor[d], 1);
        g_csr[slot] = g_src[e];
    }
}

// ---------------- fused softmax + gather + bias + relu (fp16 features) ----------------
#define CAP 96
__device__ __forceinline__ void h8_accum(const __half* p, float a, float* acc) {
    uint4 v = *(const uint4*)p;
    float2 f0 = __half22float2(*(const __half2*)&v.x);
    float2 f1 = __half22float2(*(const __half2*)&v.y);
    float2 f2 = __half22float2(*(const __half2*)&v.z);
    float2 f3 = __half22float2(*(const __half2*)&v.w);
    acc[0] += a * f0.x; acc[1] += a * f0.y;
    acc[2] += a * f1.x; acc[3] += a * f1.y;
    acc[4] += a * f2.x; acc[5] += a * f2.y;
    acc[6] += a * f3.x; acc[7] += a * f3.y;
}

__global__ __launch_bounds__(256) void gat_node_kernel(const float* __restrict__ bias,
                                                       float* __restrict__ out) {
    __shared__ float s_lg[8][CAP][4];
    __shared__ int   s_src[8][CAP];

    const int w    = threadIdx.x >> 5;
    const int lane = threadIdx.x & 31;
    const int node = (blockIdx.x * blockDim.x + threadIdx.x) >> 5;
    if (node >= N_NODES) return;
    const int n   = node;
    const int rs  = g_rowstart[n];
    const int deg = g_rowstart[n + 1] - rs;
    const int tot = deg + 1;

    float4 ad4 = *(const float4*)&g_adst[n * HEADS];
    float ad[4] = {ad4.x, ad4.y, ad4.z, ad4.w};
    const int myh = lane >> 3;

    float acc[8] = {0.f, 0.f, 0.f, 0.f, 0.f, 0.f, 0.f, 0.f};

    if (tot <= CAP) {
        float m[4] = {-CUDART_INF_F, -CUDART_INF_F, -CUDART_INF_F, -CUDART_INF_F};
        for (int i = lane; i < tot; i += 32) {
            int src = (i < deg) ? g_csr[rs + i] : n;
            s_src[w][i] = src;
            float4 a4 = *(const float4*)&g_asrc[src * HEADS];
            float lg[4] = {a4.x + ad[0], a4.y + ad[1], a4.z + ad[2], a4.w + ad[3]};
            #pragma unroll
            for (int h = 0; h < 4; h++) {
                lg[h] = lg[h] >= 0.f ? lg[h] : NEG_SLOPE * lg[h];
                m[h] = fmaxf(m[h], lg[h]);
            }
            *(float4*)&s_lg[w][i][0] = make_float4(lg[0], lg[1], lg[2], lg[3]);
        }
        #pragma unroll
        for (int off = 16; off; off >>= 1)
            #pragma unroll
            for (int h = 0; h < 4; h++)
                m[h] = fmaxf(m[h], __shfl_xor_sync(0xffffffffu, m[h], off));

        float s[4] = {0.f, 0.f, 0.f, 0.f};
        for (int i = lane; i < tot; i += 32) {
            float4 L = *(const float4*)&s_lg[w][i][0];
            float e0 = __expf(L.x - m[0]);
            float e1 = __expf(L.y - m[1]);
            float e2 = __expf(L.z - m[2]);
            float e3 = __expf(L.w - m[3]);
            s[0] += e0; s[1] += e1; s[2] += e2; s[3] += e3;
            *(float4*)&s_lg[w][i][0] = make_float4(e0, e1, e2, e3);
        }
        #pragma unroll
        for (int off = 16; off; off >>= 1)
            #pragma unroll
            for (int h = 0; h < 4; h++)
                s[h] += __shfl_xor_sync(0xffffffffu, s[h], off);

        const float inv = 1.f / (s[myh] + 1e-16f);
        __syncwarp();

        int i = 0;
        for (; i + 4 <= tot; i += 4) {
            int   sA = s_src[w][i],     sB = s_src[w][i + 1];
            int   sC = s_src[w][i + 2], sD = s_src[w][i + 3];
            float aA = s_lg[w][i][myh] * inv,     aB = s_lg[w][i + 1][myh] * inv;
            float aC = s_lg[w][i + 2][myh] * inv, aD = s_lg[w][i + 3][myh] * inv;
            h8_accum(&g_hh[(size_t)sA * HC + lane * 8], aA, acc);
            h8_accum(&g_hh[(size_t)sB * HC + lane * 8], aB, acc);
            h8_accum(&g_hh[(size_t)sC * HC + lane * 8], aC, acc);
            h8_accum(&g_hh[(size_t)sD * HC + lane * 8], aD, acc);
        }
        for (; i < tot; i++) {
            int   s0 = s_src[w][i];
            float a0 = s_lg[w][i][myh] * inv;
            h8_accum(&g_hh[(size_t)s0 * HC + lane * 8], a0, acc);
        }
    } else {
        float m[4] = {-CUDART_INF_F, -CUDART_INF_F, -CUDART_INF_F, -CUDART_INF_F};
        for (int i = lane; i < tot; i += 32) {
            int src = (i < deg) ? g_csr[rs + i] : n;
            float4 a4 = *(const float4*)&g_asrc[src * HEADS];
            float lg[4] = {a4.x + ad[0], a4.y + ad[1], a4.z + ad[2], a4.w + ad[3]};
            #pragma unroll
            for (int h = 0; h < 4; h++) {
                float v = lg[h] >= 0.f ? lg[h] : NEG_SLOPE * lg[h];
                m[h] = fmaxf(m[h], v);
            }
        }
        #pragma unroll
        for (int off = 16; off; off >>= 1)
            #pragma unroll
            for (int h = 0; h < 4; h++)
                m[h] = fmaxf(m[h], __shfl_xor_sync(0xffffffffu, m[h], off));

        float s[4] = {0.f, 0.f, 0.f, 0.f};
        for (int i = lane; i < tot; i += 32) {
            int src = (i < deg) ? g_csr[rs + i] : n;
            float4 a4 = *(const float4*)&g_asrc[src * HEADS];
            float lg[4] = {a4.x + ad[0], a4.y + ad[1], a4.z + ad[2], a4.w + ad[3]};
            #pragma unroll
            for (int h = 0; h < 4; h++) {
                float v = lg[h] >= 0.f ? lg[h] : NEG_SLOPE * lg[h];
                s[h] += __expf(v - m[h]);
            }
        }
        #pragma unroll
        for (int off = 16; off; off >>= 1)
            #pragma unroll
            for (int h = 0; h < 4; h++)
                s[h] += __shfl_xor_sync(0xffffffffu, s[h], off);

        const float mh  = m[myh];
        const float inv = 1.f / (s[myh] + 1e-16f);
        const float adh = ad[myh];
        for (int i = 0; i < tot; i++) {
            int src = (i < deg) ? g_csr[rs + i] : n;
            float av = g_asrc[src * HEADS + myh];
            float lg = av + adh;
            lg = lg >= 0.f ? lg : NEG_SLOPE * lg;
            float alpha = __expf(lg - mh) * inv;
            h8_accum(&g_hh[(size_t)src * HC + lane * 8], alpha, acc);
        }
    }

    float4 b0 = ((const float4*)bias)[lane * 2];
    float4 b1 = ((const float4*)bias)[lane * 2 + 1];
    float4 o0, o1;
    o0.x = fmaxf(acc[0] + b0.x, 0.f); o0.y = fmaxf(acc[1] + b0.y, 0.f);
    o0.z = fmaxf(acc[2] + b0.z, 0.f); o0.w = fmaxf(acc[3] + b0.w, 0.f);
    o1.x = fmaxf(acc[4] + b1.x, 0.f); o1.y = fmaxf(acc[5] + b1.y, 0.f);
    o1.z = fmaxf(acc[6] + b1.z, 0.f); o1.w = fmaxf(acc[7] + b1.w, 0.f);
    *(float4*)&out[(size_t)n * HC + lane * 8]     = o0;
    *(float4*)&out[(size_t)n * HC + lane * 8 + 4] = o1;
}

// ---------------- launch ----------------
extern "C" void kernel_launch(void* const* d_in, const int* in_sizes, int n_in,
                              void* d_out, int out_size) {
    const float* x       = (const float*)d_in[0];
    const void*  ei      = d_in[1];
    const float* W       = (const float*)d_in[2];
    const float* att_src = (const float*)d_in[3];
    const float* att_dst = (const float*)d_in[4];
    const float* bias    = (const float*)d_in[5];
    float*       out     = (float*)d_out;

    detect_kernel<<<1, 256>>>((const unsigned int*)ei);
    zero_deg_kernel<<<(N_NODES + 255) / 256, 256>>>();
    convert_kernel<<<(E_EDGES + 255) / 256, 256>>>(ei);

    dim3 tg(8, 8);
    transpose_w_kernel<<<tg, dim3(32, 8)>>>(W);

    dim3 gg(HC / GBN, (N_NODES + GBM - 1) / GBM);   // (2, 391)
    hgemm_kernel<<<gg, 256>>>(x, att_src, att_dst);

    scan_reduce_kernel<<<NSCAN, SCAN_BLK>>>();
    scan_offsets_kernel<<<1, 64>>>();
    scan_local_kernel<<<NSCAN, SCAN_BLK>>>();
    fill_kernel<<<(E_EDGES + 255) / 256, 256>>>();

    gat_node_kernel<<<(N_NODES + 7) / 8, 256>>>(bias, out);
}

// round 7
// speedup vs baseline: 3.0118x; 1.0733x over previous
#include <cuda_runtime.h>
#include <cuda_fp16.h>
#include <math_constants.h>
#include <cstdint>

#define N_NODES 50000
#define E_EDGES 800000
#define HEADS 4
#define IN_DIM 256
#define HC 256
#define NEG_SLOPE 0.2f

// ---------------- device scratch ----------------
__device__ __half g_hh[N_NODES * HC];        // x @ W in fp16 (25.6 MB)
__device__ __half g_wth[IN_DIM * HC];        // W transposed + fp16: [n][k]
__device__ float g_asrc[N_NODES * HEADS];
__device__ float g_adst[N_NODES * HEADS];
__device__ int   g_src[E_EDGES];
__device__ int   g_dst[E_EDGES];
__device__ int   g_deg[N_NODES];
__device__ int   g_rowstart[N_NODES + 1];
__device__ int   g_cursor[N_NODES];
__device__ int   g_csr[E_EDGES];
__device__ int   g_is64;
#define SCAN_BLK 1024
#define NSCAN ((N_NODES + SCAN_BLK - 1) / SCAN_BLK)   // 49
__device__ int   g_bsum[NSCAN];
__device__ int   g_boff[NSCAN];

// ---------------- host-side stream/event fork (created once at load) ----------------
struct StreamInit {
    cudaStream_t s2;
    cudaEvent_t  e1, e2;
    StreamInit() {
        cudaStreamCreateWithFlags(&s2, cudaStreamNonBlocking);
        cudaEventCreateWithFlags(&e1, cudaEventDisableTiming);
        cudaEventCreateWithFlags(&e2, cudaEventDisableTiming);
    }
};
static StreamInit g_si;

// ---------------- dtype detection ----------------
__global__ void detect_kernel(const unsigned int* __restrict__ w) {
    __shared__ unsigned int r[256];
    unsigned int acc = 0;
    for (int i = threadIdx.x; i < 8192; i += 256) acc |= w[2 * i + 1];
    r[threadIdx.x] = acc;
    __syncthreads();
    if (threadIdx.x == 0) {
        unsigned int a = 0;
        #pragma unroll 8
        for (int i = 0; i < 256; i++) a |= r[i];
        g_is64 = (a == 0u) ? 1 : 0;
    }
}

__global__ void zero_deg_kernel() {
    int i = blockIdx.x * blockDim.x + threadIdx.x;
    if (i < N_NODES) g_deg[i] = 0;
}

__global__ void convert_kernel(const void* __restrict__ ei) {
    int e = blockIdx.x * blockDim.x + threadIdx.x;
    if (e >= E_EDGES) return;
    int s, d;
    if (g_is64) {
        const long long* p = (const long long*)ei;
        s = (int)p[e];
        d = (int)p[E_EDGES + e];
    } else {
        const int* p = (const int*)ei;
        s = p[e];
        d = p[E_EDGES + e];
    }
    g_src[e] = s;
    g_dst[e] = d;
    atomicAdd(&g_deg[d], 1);
}

// ---------------- W transpose + fp16 convert (256x256) ----------------
__global__ void transpose_w_kernel(const float* __restrict__ W) {
    __shared__ float t[32][33];
    const int bx = blockIdx.x * 32, by = blockIdx.y * 32;
    #pragma unroll
    for (int i = 0; i < 4; i++)
        t[threadIdx.y + i * 8][threadIdx.x] = W[(by + threadIdx.y + i * 8) * HC + bx + threadIdx.x];
    __syncthreads();
    #pragma unroll
    for (int i = 0; i < 4; i++)
        g_wth[(bx + threadIdx.y + i * 8) * IN_DIM + by + threadIdx.x] =
            __float2half_rn(t[threadIdx.x][threadIdx.y + i * 8]);
}

// ---------------- FP16 GEMM 128x128, BK=32, ldmatrix + m16n8k16 ----------------
#define GBM 128
#define GBN 128
#define GBK 32
#define TILE_HALVES (128 * 32)

__device__ __forceinline__ void ldsm_x4(uint32_t addr, uint32_t& r0, uint32_t& r1,
                                        uint32_t& r2, uint32_t& r3) {
    asm volatile("ldmatrix.sync.aligned.m8n8.x4.shared.b16 {%0,%1,%2,%3}, [%4];"
                 : "=r"(r0), "=r"(r1), "=r"(r2), "=r"(r3) : "r"(addr));
}

__device__ __forceinline__ void mma_f16(float4& d, const uint32_t* a, const uint32_t* b) {
    asm volatile(
        "mma.sync.aligned.m16n8k16.row.col.f32.f16.f16.f32 "
        "{%0,%1,%2,%3}, {%4,%5,%6,%7}, {%8,%9}, {%0,%1,%2,%3};\n"
        : "+f"(d.x), "+f"(d.y), "+f"(d.z), "+f"(d.w)
        : "r"(a[0]), "r"(a[1]), "r"(a[2]), "r"(a[3]),
          "r"(b[0]), "r"(b[1]));
}

__global__ __launch_bounds__(256, 2) void hgemm_kernel(
    const float* __restrict__ x,
    const float* __restrict__ att_src, const float* __restrict__ att_dst) {
    __shared__ __align__(16) __half As[2][TILE_HALVES];
    __shared__ __align__(16) __half Bs[2][TILE_HALVES];

    const int tid  = threadIdx.x;
    const int w    = tid >> 5;
    const int lane = tid & 31;
    const int gid  = lane >> 2;
    const int tig  = lane & 3;
    const int wm   = w & 3;
    const int wn   = w >> 2;
    const int rowblk = blockIdx.y * GBM;
    const int col0   = blockIdx.x * GBN;

    float4 acc[2][8];
    #pragma unroll
    for (int i = 0; i < 2; i++)
        #pragma unroll
        for (int j = 0; j < 8; j++) acc[i][j] = make_float4(0.f, 0.f, 0.f, 0.f);

    const int l_row = tid >> 1;
    const int hs    = tid & 1;
    int a_grow = rowblk + l_row;
    if (a_grow > N_NODES - 1) a_grow = N_NODES - 1;
    const int b_grow = col0 + l_row;

    const int swq  = (l_row >> 1) & 3;
    const int c0   = hs * 2;
    const int sts0 = l_row * 32 + ((c0 ^ swq) << 3);
    const int sts1 = l_row * 32 + (((c0 + 1) ^ swq) << 3);

    const int lr  = lane & 15;
    const int csl = lane >> 4;
    const int q2  = (lr >> 1) & 3;
    const uint32_t loff0 = lr * 64 + (((0 + csl) ^ q2) << 4);
    const uint32_t loff1 = lr * 64 + (((2 + csl) ^ q2) << 4);

    const uint32_t aB0 = (uint32_t)__cvta_generic_to_shared(&As[0][0]);
    const uint32_t aB1 = (uint32_t)__cvta_generic_to_shared(&As[1][0]);
    const uint32_t bB0 = (uint32_t)__cvta_generic_to_shared(&Bs[0][0]);
    const uint32_t bB1 = (uint32_t)__cvta_generic_to_shared(&Bs[1][0]);

    float4 ar0, ar1, ar2, ar3;
    uint4  br0, br1;
    auto ldgA = [&](int k0) {
        const float* p = &x[(size_t)a_grow * IN_DIM + k0 + hs * 16];
        ar0 = *(const float4*)p;
        ar1 = *(const float4*)(p + 4);
        ar2 = *(const float4*)(p + 8);
        ar3 = *(const float4*)(p + 12);
    };
    auto ldgB = [&](int k0) {
        const uint4* p = (const uint4*)&g_wth[(size_t)b_grow * IN_DIM + k0 + hs * 16];
        br0 = p[0];
        br1 = p[1];
    };
    auto stsA = [&](int buf) {
        __half* d = As[buf];
        __align__(16) __half2 t0[4], t1[4];
        t0[0] = __floats2half2_rn(ar0.x, ar0.y);
        t0[1] = __floats2half2_rn(ar0.z, ar0.w);
        t0[2] = __floats2half2_rn(ar1.x, ar1.y);
        t0[3] = __floats2half2_rn(ar1.z, ar1.w);
        t1[0] = __floats2half2_rn(ar2.x, ar2.y);
        t1[1] = __floats2half2_rn(ar2.z, ar2.w);
        t1[2] = __floats2half2_rn(ar3.x, ar3.y);
        t1[3] = __floats2half2_rn(ar3.z, ar3.w);
        *(uint4*)&d[sts0] = *(const uint4*)t0;
        *(uint4*)&d[sts1] = *(const uint4*)t1;
    };
    auto stsB = [&](int buf) {
        __half* d = Bs[buf];
        *(uint4*)&d[sts0] = br0;
        *(uint4*)&d[sts1] = br1;
    };

    auto compute = [&](int buf) {
        const uint32_t Ab = buf ? aB1 : aB0;
        const uint32_t Bb = buf ? bB1 : bB0;
        #pragma unroll
        for (int kbi = 0; kbi < 2; kbi++) {
            const uint32_t lo = kbi ? loff1 : loff0;
            uint32_t afr[2][4], bfr[8][2];
            #pragma unroll
            for (int mt = 0; mt < 2; mt++) {
                uint32_t addr = Ab + (uint32_t)((wm * 32 + mt * 16) * 64) + lo;
                ldsm_x4(addr, afr[mt][0], afr[mt][1], afr[mt][2], afr[mt][3]);
            }
            #pragma unroll
            for (int ntp = 0; ntp < 4; ntp++) {
                uint32_t addr = Bb + (uint32_t)((wn * 64 + ntp * 16) * 64) + lo;
                ldsm_x4(addr, bfr[2 * ntp][0], bfr[2 * ntp + 1][0],
                              bfr[2 * ntp][1], bfr[2 * ntp + 1][1]);
            }
            #pragma unroll
            for (int mt = 0; mt < 2; mt++)
                #pragma unroll
                for (int nt = 0; nt < 8; nt++)
                    mma_f16(acc[mt][nt], afr[mt], bfr[nt]);
        }
    };

    ldgA(0); ldgB(0);
    stsA(0); stsB(0);
    ldgA(GBK); ldgB(GBK);
    __syncthreads();

    const int NIT = IN_DIM / GBK;   // 8
    for (int it = 0; it < NIT; ++it) {
        if (it + 1 < NIT) { stsA((it + 1) & 1); stsB((it + 1) & 1); }
        if (it + 2 < NIT) { ldgA((it + 2) * GBK); ldgB((it + 2) * GBK); }
        compute(it & 1);
        __syncthreads();
    }

    // epilogue: store h (fp16) + fused attention dots (warp cols = one head)
    const int head = blockIdx.x * 2 + wn;
    float2 avs[8], avd[8];
    #pragma unroll
    for (int nt = 0; nt < 8; nt++) {
        int c = col0 + wn * 64 + nt * 8 + tig * 2;
        avs[nt] = *(const float2*)&att_src[c];
        avd[nt] = *(const float2*)&att_dst[c];
    }

    #pragma unroll
    for (int mt = 0; mt < 2; mt++) {
        int row0 = rowblk + wm * 32 + mt * 16 + gid;
        int row1 = row0 + 8;
        float s0 = 0.f, s1 = 0.f, t0 = 0.f, t1 = 0.f;
        #pragma unroll
        for (int nt = 0; nt < 8; nt++) {
            float4 d = acc[mt][nt];
            int col = col0 + wn * 64 + nt * 8 + tig * 2;
            if (row0 < N_NODES)
                *(__half2*)&g_hh[(size_t)row0 * HC + col] = __floats2half2_rn(d.x, d.y);
            if (row1 < N_NODES)
                *(__half2*)&g_hh[(size_t)row1 * HC + col] = __floats2half2_rn(d.z, d.w);
            s0 += d.x * avs[nt].x + d.y * avs[nt].y;
            s1 += d.z * avs[nt].x + d.w * avs[nt].y;
            t0 += d.x * avd[nt].x + d.y * avd[nt].y;
            t1 += d.z * avd[nt].x + d.w * avd[nt].y;
        }
        #pragma unroll
        for (int off = 1; off <= 2; off <<= 1) {
            s0 += __shfl_xor_sync(0xffffffffu, s0, off);
            s1 += __shfl_xor_sync(0xffffffffu, s1, off);
            t0 += __shfl_xor_sync(0xffffffffu, t0, off);
            t1 += __shfl_xor_sync(0xffffffffu, t1, off);
        }
        if (tig == 0) {
            if (row0 < N_NODES) { g_asrc[row0 * HEADS + head] = s0; g_adst[row0 * HEADS + head] = t0; }
            if (row1 < N_NODES) { g_asrc[row1 * HEADS + head] = s1; g_adst[row1 * HEADS + head] = t1; }
        }
    }
}

// ---------------- multi-block scan ----------------
__global__ void scan_reduce_kernel() {
    __shared__ int ws[32];
    int i = blockIdx.x * SCAN_BLK + threadIdx.x;
    int v = (i < N_NODES) ? g_deg[i] : 0;
    #pragma unroll
    for (int off = 16; off; off >>= 1) v += __shfl_xor_sync(0xffffffffu, v, off);
    if ((threadIdx.x & 31) == 0) ws[threadIdx.x >> 5] = v;
    __syncthreads();
    if (threadIdx.x < 32) {
        int t = ws[threadIdx.x];
        #pragma unroll
        for (int off = 16; off; off >>= 1) t += __shfl_xor_sync(0xffffffffu, t, off);
        if (threadIdx.x == 0) g_bsum[blockIdx.x] = t;
    }
}

__global__ void scan_offsets_kernel() {
    __shared__ int tmp[64];
    int t = threadIdx.x;
    int v = (t < NSCAN) ? g_bsum[t] : 0;
    tmp[t] = v;
    __syncthreads();
    #pragma unroll
    for (int off = 1; off < 64; off <<= 1) {
        int a = (t >= off) ? tmp[t - off] : 0;
        __syncthreads();
        tmp[t] += a;
        __syncthreads();
    }
    if (t < NSCAN) g_boff[t] = tmp[t] - v;
    if (t == NSCAN - 1) g_rowstart[N_NODES] = tmp[t];
}

__global__ void scan_local_kernel() {
    __shared__ int wsums[32];
    const int tid = threadIdx.x, wid = tid >> 5, lane = tid & 31;
    int i = blockIdx.x * SCAN_BLK + tid;
    int v = (i < N_NODES) ? g_deg[i] : 0;
    int incl = v;
    #pragma unroll
    for (int off = 1; off < 32; off <<= 1) {
        int t = __shfl_up_sync(0xffffffffu, incl, off);
        if (lane >= off) incl += t;
    }
    if (lane == 31) wsums[wid] = incl;
    __syncthreads();
    if (wid == 0) {
        int wv = wsums[lane];
        #pragma unroll
        for (int off = 1; off < 32; off <<= 1) {
            int t = __shfl_up_sync(0xffffffffu, wv, off);
            if (lane >= off) wv += t;
        }
        wsums[lane] = wv;
    }
    __syncthreads();
    if (i < N_NODES) {
        int start = g_boff[blockIdx.x] + ((wid > 0) ? wsums[wid - 1] : 0) + incl - v;
        g_rowstart[i] = start;
        g_cursor[i]   = start;
    }
}

__global__ void fill_kernel() {
    int e = blockIdx.x * blockDim.x + threadIdx.x;
    if (e < E_EDGES) {
        int d = g_dst[e];
        int slot = atomicAdd(&g_cursor[d], 1);
        g_csr[slot] = g_src[e];
    }
}

// ---------------- fused softmax + gather + bias + relu (fp16 features) ----------------
#define CAP 96
__device__ __forceinline__ void h8_accum(const __half* p, float a, float* acc) {
    uint4 v = *(const uint4*)p;
    float2 f0 = __half22float2(*(const __half2*)&v.x);
    float2 f1 = __half22float2(*(const __half2*)&v.y);
    float2 f2 = __half22float2(*(const __half2*)&v.z);
    float2 f3 = __half22float2(*(const __half2*)&v.w);
    acc[0] += a * f0.x; acc[1] += a * f0.y;
    acc[2] += a * f1.x; acc[3] += a * f1.y;
    acc[4] += a * f2.x; acc[5] += a * f2.y;
    acc[6] += a * f3.x; acc[7] += a * f3.y;
}

__global__ __launch_bounds__(256) void gat_node_kernel(const float* __restrict__ bias,
                                                       float* __restrict__ out) {
    __shared__ float s_lg[8][CAP][4];
    __shared__ int   s_src[8][CAP];

    const int w    = threadIdx.x >> 5;
    const int lane = threadIdx.x & 31;
    const int node = (blockIdx.x * blockDim.x + threadIdx.x) >> 5;
    if (node >= N_NODES) return;
    const int n   = node;
    const int rs  = g_rowstart[n];
    const int deg = g_rowstart[n + 1] - rs;
    const int tot = deg + 1;

    float4 ad4 = *(const float4*)&g_adst[n * HEADS];
    float ad[4] = {ad4.x, ad4.y, ad4.z, ad4.w};
    const int myh = lane >> 3;

    float acc[8] = {0.f, 0.f, 0.f, 0.f, 0.f, 0.f, 0.f, 0.f};

    if (tot <= CAP) {
        float m[4] = {-CUDART_INF_F, -CUDART_INF_F, -CUDART_INF_F, -CUDART_INF_F};
        for (int i = lane; i < tot; i += 32) {
            int src = (i < deg) ? g_csr[rs + i] : n;
            s_src[w][i] = src;
            float4 a4 = *(const float4*)&g_asrc[src * HEADS];
            float lg[4] = {a4.x + ad[0], a4.y + ad[1], a4.z + ad[2], a4.w + ad[3]};
            #pragma unroll
            for (int h = 0; h < 4; h++) {
                lg[h] = lg[h] >= 0.f ? lg[h] : NEG_SLOPE * lg[h];
                m[h] = fmaxf(m[h], lg[h]);
            }
            *(float4*)&s_lg[w][i][0] = make_float4(lg[0], lg[1], lg[2], lg[3]);
        }
        #pragma unroll
        for (int off = 16; off; off >>= 1)
            #pragma unroll
            for (int h = 0; h < 4; h++)
                m[h] = fmaxf(m[h], __shfl_xor_sync(0xffffffffu, m[h], off));

        float s[4] = {0.f, 0.f, 0.f, 0.f};
        for (int i = lane; i < tot; i += 32) {
            float4 L = *(const float4*)&s_lg[w][i][0];
            float e0 = __expf(L.x - m[0]);
            float e1 = __expf(L.y - m[1]);
            float e2 = __expf(L.z - m[2]);
            float e3 = __expf(L.w - m[3]);
            s[0] += e0; s[1] += e1; s[2] += e2; s[3] += e3;
            *(float4*)&s_lg[w][i][0] = make_float4(e0, e1, e2, e3);
        }
        #pragma unroll
        for (int off = 16; off; off >>= 1)
            #pragma unroll
            for (int h = 0; h < 4; h++)
                s[h] += __shfl_xor_sync(0xffffffffu, s[h], off);

        const float inv = 1.f / (s[myh] + 1e-16f);
        __syncwarp();

        int i = 0;
        for (; i + 4 <= tot; i += 4) {
            int   sA = s_src[w][i],     sB = s_src[w][i + 1];
            int   sC = s_src[w][i + 2], sD = s_src[w][i + 3];
            float aA = s_lg[w][i][myh] * inv,     aB = s_lg[w][i + 1][myh] * inv;
            float aC = s_lg[w][i + 2][myh] * inv, aD = s_lg[w][i + 3][myh] * inv;
            h8_accum(&g_hh[(size_t)sA * HC + lane * 8], aA, acc);
            h8_accum(&g_hh[(size_t)sB * HC + lane * 8], aB, acc);
            h8_accum(&g_hh[(size_t)sC * HC + lane * 8], aC, acc);
            h8_accum(&g_hh[(size_t)sD * HC + lane * 8], aD, acc);
        }
        for (; i < tot; i++) {
            int   s0 = s_src[w][i];
            float a0 = s_lg[w][i][myh] * inv;
            h8_accum(&g_hh[(size_t)s0 * HC + lane * 8], a0, acc);
        }
    } else {
        float m[4] = {-CUDART_INF_F, -CUDART_INF_F, -CUDART_INF_F, -CUDART_INF_F};
        for (int i = lane; i < tot; i += 32) {
            int src = (i < deg) ? g_csr[rs + i] : n;
            float4 a4 = *(const float4*)&g_asrc[src * HEADS];
            float lg[4] = {a4.x + ad[0], a4.y + ad[1], a4.z + ad[2], a4.w + ad[3]};
            #pragma unroll
            for (int h = 0; h < 4; h++) {
                float v = lg[h] >= 0.f ? lg[h] : NEG_SLOPE * lg[h];
                m[h] = fmaxf(m[h], v);
            }
        }
        #pragma unroll
        for (int off = 16; off; off >>= 1)
            #pragma unroll
            for (int h = 0; h < 4; h++)
                m[h] = fmaxf(m[h], __shfl_xor_sync(0xffffffffu, m[h], off));

        float s[4] = {0.f, 0.f, 0.f, 0.f};
        for (int i = lane; i < tot; i += 32) {
            int src = (i < deg) ? g_csr[rs + i] : n;
            float4 a4 = *(const float4*)&g_asrc[src * HEADS];
            float lg[4] = {a4.x + ad[0], a4.y + ad[1], a4.z + ad[2], a4.w + ad[3]};
            #pragma unroll
            for (int h = 0; h < 4; h++) {
                float v = lg[h] >= 0.f ? lg[h] : NEG_SLOPE * lg[h];
                s[h] += __expf(v - m[h]);
            }
        }
        #pragma unroll
        for (int off = 16; off; off >>= 1)
            #pragma unroll
            for (int h = 0; h < 4; h++)
                s[h] += __shfl_xor_sync(0xffffffffu, s[h], off);

        const float mh  = m[myh];
        const float inv = 1.f / (s[myh] + 1e-16f);
        const float adh = ad[myh];
        for (int i = 0; i < tot; i++) {
            int src = (i < deg) ? g_csr[rs + i] : n;
            float av = g_asrc[src * HEADS + myh];
            float lg = av + adh;
            lg = lg >= 0.f ? lg : NEG_SLOPE * lg;
            float alpha = __expf(lg - mh) * inv;
            h8_accum(&g_hh[(size_t)src * HC + lane * 8], alpha, acc);
        }
    }

    float4 b0 = ((const float4*)bias)[lane * 2];
    float4 b1 = ((const float4*)bias)[lane * 2 + 1];
    float4 o0, o1;
    o0.x = fmaxf(acc[0] + b0.x, 0.f); o0.y = fmaxf(acc[1] + b0.y, 0.f);
    o0.z = fmaxf(acc[2] + b0.z, 0.f); o0.w = fmaxf(acc[3] + b0.w, 0.f);
    o1.x = fmaxf(acc[4] + b1.x, 0.f); o1.y = fmaxf(acc[5] + b1.y, 0.f);
    o1.z = fmaxf(acc[6] + b1.z, 0.f); o1.w = fmaxf(acc[7] + b1.w, 0.f);
    *(float4*)&out[(size_t)n * HC + lane * 8]     = o0;
    *(float4*)&out[(size_t)n * HC + lane * 8 + 4] = o1;
}

// ---------------- launch: fork CSR build onto side stream, join before gather ----------------
extern "C" void kernel_launch(void* const* d_in, const int* in_sizes, int n_in,
                              void* d_out, int out_size) {
    const float* x       = (const float*)d_in[0];
    const void*  ei      = d_in[1];
    const float* W       = (const float*)d_in[2];
    const float* att_src = (const float*)d_in[3];
    const float* att_dst = (const float*)d_in[4];
    const float* bias    = (const float*)d_in[5];
    float*       out     = (float*)d_out;

    // fork: side stream handles the CSR build chain
    cudaEventRecord(g_si.e1, 0);
    cudaStreamWaitEvent(g_si.s2, g_si.e1, 0);

    detect_kernel<<<1, 256, 0, g_si.s2>>>((const unsigned int*)ei);
    zero_deg_kernel<<<(N_NODES + 255) / 256, 256, 0, g_si.s2>>>();
    convert_kernel<<<(E_EDGES + 255) / 256, 256, 0, g_si.s2>>>(ei);
    scan_reduce_kernel<<<NSCAN, SCAN_BLK, 0, g_si.s2>>>();
    scan_offsets_kernel<<<1, 64, 0, g_si.s2>>>();
    scan_local_kernel<<<NSCAN, SCAN_BLK, 0, g_si.s2>>>();
    fill_kernel<<<(E_EDGES + 255) / 256, 256, 0, g_si.s2>>>();
    cudaEventRecord(g_si.e2, g_si.s2);

    // main stream: transpose + GEMM (independent of CSR build)
    dim3 tg(8, 8);
    transpose_w_kernel<<<tg, dim3(32, 8)>>>(W);
    dim3 gg(HC / GBN, (N_NODES + GBM - 1) / GBM);   // (2, 391)
    hgemm_kernel<<<gg, 256>>>(x, att_src, att_dst);

    // join: gather needs both chains
    cudaStreamWaitEvent(0, g_si.e2, 0);
    gat_node_kernel<<<(N_NODES + 7) / 8, 256>>>(bias, out);
}

// round 9
// speedup vs baseline: 3.2231x; 1.0702x over previous
#include <cuda_runtime.h>
#include <cuda_fp16.h>
#include <math_constants.h>
#include <cstdint>

#define N_NODES 50000
#define E_EDGES 800000
#define HEADS 4
#define IN_DIM 256
#define HC 256
#define NEG_SLOPE 0.2f

// ---------------- device scratch ----------------
__device__ __half g_hh[N_NODES * HC];        // x @ W in fp16 (25.6 MB)
__device__ __half g_xh[N_NODES * IN_DIM];    // x in fp16 (25.6 MB)
__device__ __half g_wth[IN_DIM * HC];        // W transposed + fp16: [n][k]
__device__ float g_asrc[N_NODES * HEADS];
__device__ float g_adst[N_NODES * HEADS];
__device__ int   g_src[E_EDGES];
__device__ int   g_dst[E_EDGES];
__device__ int   g_deg[N_NODES];
__device__ int   g_rowstart[N_NODES + 1];
__device__ int   g_cursor[N_NODES];
__device__ int   g_csr[E_EDGES];
__device__ int   g_is64;
#define SCAN_BLK 1024
#define NSCAN ((N_NODES + SCAN_BLK - 1) / SCAN_BLK)   // 49
__device__ int   g_bsum[NSCAN];
__device__ int   g_boff[NSCAN];

// ---------------- host-side stream/event fork ----------------
struct StreamInit {
    cudaStream_t s2;
    cudaEvent_t  e1, e2, e3;
    StreamInit() {
        cudaStreamCreateWithFlags(&s2, cudaStreamNonBlocking);
        cudaEventCreateWithFlags(&e1, cudaEventDisableTiming);
        cudaEventCreateWithFlags(&e2, cudaEventDisableTiming);
        cudaEventCreateWithFlags(&e3, cudaEventDisableTiming);
    }
};
static StreamInit g_si;

// ---------------- dtype detection ----------------
__global__ void detect_kernel(const unsigned int* __restrict__ w) {
    __shared__ unsigned int r[256];
    unsigned int acc = 0;
    for (int i = threadIdx.x; i < 8192; i += 256) acc |= w[2 * i + 1];
    r[threadIdx.x] = acc;
    __syncthreads();
    if (threadIdx.x == 0) {
        unsigned int a = 0;
        #pragma unroll 8
        for (int i = 0; i < 256; i++) a |= r[i];
        g_is64 = (a == 0u) ? 1 : 0;
    }
}

__global__ void zero_deg_kernel() {
    int i = blockIdx.x * blockDim.x + threadIdx.x;
    if (i < N_NODES) g_deg[i] = 0;
}

__global__ void convert_kernel(const void* __restrict__ ei) {
    int e = blockIdx.x * blockDim.x + threadIdx.x;
    if (e >= E_EDGES) return;
    int s, d;
    if (g_is64) {
        const long long* p = (const long long*)ei;
        s = (int)p[e];
        d = (int)p[E_EDGES + e];
    } else {
        const int* p = (const int*)ei;
        s = p[e];
        d = p[E_EDGES + e];
    }
    g_src[e] = s;
    g_dst[e] = d;
    atomicAdd(&g_deg[d], 1);
}

// ---------------- x -> fp16 conversion ----------------
__global__ void convert_x_kernel(const float* __restrict__ x) {
    int i = blockIdx.x * blockDim.x + threadIdx.x;   // one per 8 elems
    const int total = N_NODES * IN_DIM / 8;
    if (i >= total) return;
    const float4* p = (const float4*)&x[(size_t)i * 8];
    float4 f0 = p[0], f1 = p[1];
    __align__(16) __half2 h[4];
    h[0] = __floats2half2_rn(f0.x, f0.y);
    h[1] = __floats2half2_rn(f0.z, f0.w);
    h[2] = __floats2half2_rn(f1.x, f1.y);
    h[3] = __floats2half2_rn(f1.z, f1.w);
    *(uint4*)&g_xh[(size_t)i * 8] = *(const uint4*)h;
}

// ---------------- W transpose + fp16 convert ----------------
__global__ void transpose_w_kernel(const float* __restrict__ W) {
    __shared__ float t[32][33];
    const int bx = blockIdx.x * 32, by = blockIdx.y * 32;
    #pragma unroll
    for (int i = 0; i < 4; i++)
        t[threadIdx.y + i * 8][threadIdx.x] = W[(by + threadIdx.y + i * 8) * HC + bx + threadIdx.x];
    __syncthreads();
    #pragma unroll
    for (int i = 0; i < 4; i++)
        g_wth[(bx + threadIdx.y + i * 8) * IN_DIM + by + threadIdx.x] =
            __float2half_rn(t[threadIdx.x][threadIdx.y + i * 8]);
}

// ---------------- FP16 GEMM 128x128, BK=32, cp.async 4-stage + m16n8k16 ----------------
#define GBM 128
#define GBN 128
#define GBK 32
#define STAGES 4
#define STAGE_BYTES 16384          // A 8KB + B 8KB
#define GEMM_SMEM (STAGES * STAGE_BYTES)

__device__ __forceinline__ void ldsm_x4(uint32_t addr, uint32_t& r0, uint32_t& r1,
                                        uint32_t& r2, uint32_t& r3) {
    asm volatile("ldmatrix.sync.aligned.m8n8.x4.shared.b16 {%0,%1,%2,%3}, [%4];"
                 : "=r"(r0), "=r"(r1), "=r"(r2), "=r"(r3) : "r"(addr));
}

__device__ __forceinline__ void mma_f16(float4& d, const uint32_t* a, const uint32_t* b) {
    asm volatile(
        "mma.sync.aligned.m16n8k16.row.col.f32.f16.f16.f32 "
        "{%0,%1,%2,%3}, {%4,%5,%6,%7}, {%8,%9}, {%0,%1,%2,%3};\n"
        : "+f"(d.x), "+f"(d.y), "+f"(d.z), "+f"(d.w)
        : "r"(a[0]), "r"(a[1]), "r"(a[2]), "r"(a[3]),
          "r"(b[0]), "r"(b[1]));
}

__device__ __forceinline__ void cp_async16(uint32_t dst, const void* src) {
    asm volatile("cp.async.cg.shared.global [%0], [%1], 16;" :: "r"(dst), "l"(src));
}
__device__ __forceinline__ void cp_commit() {
    asm volatile("cp.async.commit_group;" ::: "memory");
}
#define CP_WAIT2() asm volatile("cp.async.wait_group 2;" ::: "memory")

__global__ __launch_bounds__(256, 2) void hgemm_kernel(
    const float* __restrict__ att_src, const float* __restrict__ att_dst) {
    extern __shared__ __align__(16) char smem[];

    const int tid  = threadIdx.x;
    const int w    = tid >> 5;
    const int lane = tid & 31;
    const int gid  = lane >> 2;
    const int tig  = lane & 3;
    const int wm   = w & 3;
    const int wn   = w >> 2;
    const int rowblk = blockIdx.y * GBM;
    const int col0   = blockIdx.x * GBN;

    float4 acc[2][8];
    #pragma unroll
    for (int i = 0; i < 2; i++)
        #pragma unroll
        for (int j = 0; j < 8; j++) acc[i][j] = make_float4(0.f, 0.f, 0.f, 0.f);

    const uint32_t sbase = (uint32_t)__cvta_generic_to_shared(smem);

    // chunk mapping: per 16B chunk c in 0..511 : row=c>>2, kc=c&3
    // dst (bytes) = row*64 + ((kc ^ ((row>>1)&3))<<4)
    const int c_a  = tid;          // chunks c and c+256 per thread for A and B
    auto dst_off = [&](int c) {
        int row = c >> 2, kc = c & 3;
        return (uint32_t)(row * 64 + (((kc) ^ ((row >> 1) & 3)) << 4));
    };
    const uint32_t dA0 = dst_off(c_a), dA1 = dst_off(c_a + 256);
    // global row/k per chunk for A
    int arow0 = rowblk + (c_a >> 2);         if (arow0 > N_NODES - 1) arow0 = N_NODES - 1;
    int arow1 = rowblk + ((c_a + 256) >> 2); if (arow1 > N_NODES - 1) arow1 = N_NODES - 1;
    const int akc0 = (c_a & 3) * 8, akc1 = ((c_a + 256) & 3) * 8;   // halves within BK
    const int brow0 = col0 + (c_a >> 2);
    const int brow1 = col0 + ((c_a + 256) >> 2);

    auto issue_stage = [&](int it) {
        const uint32_t sb = sbase + (uint32_t)((it & 3) * STAGE_BYTES);
        const int k0 = it * GBK;   // halves
        cp_async16(sb + dA0,        &g_xh[(size_t)arow0 * IN_DIM + k0 + akc0]);
        cp_async16(sb + dA1,        &g_xh[(size_t)arow1 * IN_DIM + k0 + akc1]);
        cp_async16(sb + 8192 + dA0, &g_wth[(size_t)brow0 * IN_DIM + k0 + akc0]);
        cp_async16(sb + 8192 + dA1, &g_wth[(size_t)brow1 * IN_DIM + k0 + akc1]);
    };

    // ldmatrix lane offsets (bytes): 64B rows, 4 chunks of 16B
    const int lr  = lane & 15;
    const int csl = lane >> 4;
    const int q2  = (lr >> 1) & 3;
    const uint32_t loff0 = lr * 64 + (((0 + csl) ^ q2) << 4);
    const uint32_t loff1 = lr * 64 + (((2 + csl) ^ q2) << 4);

    auto compute = [&](int it) {
        const uint32_t Ab = sbase + (uint32_t)((it & 3) * STAGE_BYTES);
        const uint32_t Bb = Ab + 8192;
        #pragma unroll
        for (int kbi = 0; kbi < 2; kbi++) {
            const uint32_t lo = kbi ? loff1 : loff0;
            uint32_t afr[2][4], bfr[8][2];
            #pragma unroll
            for (int mt = 0; mt < 2; mt++) {
                uint32_t addr = Ab + (uint32_t)((wm * 32 + mt * 16) * 64) + lo;
                ldsm_x4(addr, afr[mt][0], afr[mt][1], afr[mt][2], afr[mt][3]);
            }
            #pragma unroll
            for (int ntp = 0; ntp < 4; ntp++) {
                uint32_t addr = Bb + (uint32_t)((wn * 64 + ntp * 16) * 64) + lo;
                ldsm_x4(addr, bfr[2 * ntp][0], bfr[2 * ntp + 1][0],
                              bfr[2 * ntp][1], bfr[2 * ntp + 1][1]);
            }
            #pragma unroll
            for (int mt = 0; mt < 2; mt++)
                #pragma unroll
                for (int nt = 0; nt < 8; nt++)
                    mma_f16(acc[mt][nt], afr[mt], bfr[nt]);
        }
    };

    const int NIT = IN_DIM / GBK;   // 8
    // prologue: stages 0..2
    #pragma unroll
    for (int s = 0; s < STAGES - 1; s++) { issue_stage(s); cp_commit(); }

    for (int it = 0; it < NIT; ++it) {
        CP_WAIT2();
        __syncthreads();
        if (it + STAGES - 1 < NIT) issue_stage(it + STAGES - 1);
        cp_commit();
        compute(it);
    }

    // epilogue: store h (fp16) + fused attention dots (warp cols = one head)
    const int head = blockIdx.x * 2 + wn;
    float2 avs[8], avd[8];
    #pragma unroll
    for (int nt = 0; nt < 8; nt++) {
        int c = col0 + wn * 64 + nt * 8 + tig * 2;
        avs[nt] = *(const float2*)&att_src[c];
        avd[nt] = *(const float2*)&att_dst[c];
    }

    #pragma unroll
    for (int mt = 0; mt < 2; mt++) {
        int row0 = rowblk + wm * 32 + mt * 16 + gid;
        int row1 = row0 + 8;
        float s0 = 0.f, s1 = 0.f, t0 = 0.f, t1 = 0.f;
        #pragma unroll
        for (int nt = 0; nt < 8; nt++) {
            float4 d = acc[mt][nt];
            int col = col0 + wn * 64 + nt * 8 + tig * 2;
            if (row0 < N_NODES)
                *(__half2*)&g_hh[(size_t)row0 * HC + col] = __floats2half2_rn(d.x, d.y);
            if (row1 < N_NODES)
                *(__half2*)&g_hh[(size_t)row1 * HC + col] = __floats2half2_rn(d.z, d.w);
            s0 += d.x * avs[nt].x + d.y * avs[nt].y;
            s1 += d.z * avs[nt].x + d.w * avs[nt].y;
            t0 += d.x * avd[nt].x + d.y * avd[nt].y;
            t1 += d.z * avd[nt].x + d.w * avd[nt].y;
        }
        #pragma unroll
        for (int off = 1; off <= 2; off <<= 1) {
            s0 += __shfl_xor_sync(0xffffffffu, s0, off);
            s1 += __shfl_xor_sync(0xffffffffu, s1, off);
            t0 += __shfl_xor_sync(0xffffffffu, t0, off);
            t1 += __shfl_xor_sync(0xffffffffu, t1, off);
        }
        if (tig == 0) {
            if (row0 < N_NODES) { g_asrc[row0 * HEADS + head] = s0; g_adst[row0 * HEADS + head] = t0; }
            if (row1 < N_NODES) { g_asrc[row1 * HEADS + head] = s1; g_adst[row1 * HEADS + head] = t1; }
        }
    }
}

// ---------------- multi-block scan ----------------
__global__ void scan_reduce_kernel() {
    __shared__ int ws[32];
    int i = blockIdx.x * SCAN_BLK + threadIdx.x;
    int v = (i < N_NODES) ? g_deg[i] : 0;
    #pragma unroll
    for (int off = 16; off; off >>= 1) v += __shfl_xor_sync(0xffffffffu, v, off);
    if ((threadIdx.x & 31) == 0) ws[threadIdx.x >> 5] = v;
    __syncthreads();
    if (threadIdx.x < 32) {
        int t = ws[threadIdx.x];
        #pragma unroll
        for (int off = 16; off; off >>= 1) t += __shfl_xor_sync(0xffffffffu, t, off);
        if (threadIdx.x == 0) g_bsum[blockIdx.x] = t;
    }
}

__global__ void scan_offsets_kernel() {
    __shared__ int tmp[64];
    int t = threadIdx.x;
    int v = (t < NSCAN) ? g_bsum[t] : 0;
    tmp[t] = v;
    __syncthreads();
    #pragma unroll
    for (int off = 1; off < 64; off <<= 1) {
        int a = (t >= off) ? tmp[t - off] : 0;
        __syncthreads();
        tmp[t] += a;
        __syncthreads();
    }
    if (t < NSCAN) g_boff[t] = tmp[t] - v;
    if (t == NSCAN - 1) g_rowstart[N_NODES] = tmp[t];
}

__global__ void scan_local_kernel() {
    __shared__ int wsums[32];
    const int tid = threadIdx.x, wid = tid >> 5, lane = tid & 31;
    int i = blockIdx.x * SCAN_BLK + tid;
    int v = (i < N_NODES) ? g_deg[i] : 0;
    int incl = v;
    #pragma unroll
    for (int off = 1; off < 32; off <<= 1) {
        int t = __shfl_up_sync(0xffffffffu, incl, off);
        if (lane >= off) incl += t;
    }
    if (lane == 31) wsums[wid] = incl;
    __syncthreads();
    if (wid == 0) {
        int wv = wsums[lane];
        #pragma unroll
        for (int off = 1; off < 32; off <<= 1) {
            int t = __shfl_up_sync(0xffffffffu, wv, off);
            if (lane >= off) wv += t;
        }
        wsums[lane] = wv;
    }
    __syncthreads();
    if (i < N_NODES) {
        int start = g_boff[blockIdx.x] + ((wid > 0) ? wsums[wid - 1] : 0) + incl - v;
        g_rowstart[i] = start;
        g_cursor[i]   = start;
    }
}

__global__ void fill_kernel() {
    int e = blockIdx.x * blockDim.x + threadIdx.x;
    if (e < E_EDGES) {
        int d = g_dst[e];
        int slot = atomicAdd(&g_cursor[d], 1);
        g_csr[slot] = g_src[e];
    }
}

// ---------------- fused softmax + gather + bias + relu (fp16 features) ----------------
#define CAP 96
__device__ __forceinline__ void h8_accum(const __half* p, float a, float* acc) {
    uint4 v = *(const uint4*)p;
    float2 f0 = __half22float2(*(const __half2*)&v.x);
    float2 f1 = __half22float2(*(const __half2*)&v.y);
    float2 f2 = __half22float2(*(const __half2*)&v.z);
    float2 f3 = __half22float2(*(const __half2*)&v.w);
    acc[0] += a * f0.x; acc[1] += a * f0.y;
    acc[2] += a * f1.x; acc[3] += a * f1.y;
    acc[4] += a * f2.x; acc[5] += a * f2.y;
    acc[6] += a * f3.x; acc[7] += a * f3.y;
}

__global__ __launch_bounds__(256) void gat_node_kernel(const float* __restrict__ bias,
                                                       float* __restrict__ out) {
    __shared__ float s_lg[8][CAP][4];
    __shared__ int   s_src[8][CAP];

    const int w    = threadIdx.x >> 5;
    const int lane = threadIdx.x & 31;
    const int node = (blockIdx.x * blockDim.x + threadIdx.x) >> 5;
    if (node >= N_NODES) return;
    const int n   = node;
    const int rs  = g_rowstart[n];
    const int deg = g_rowstart[n + 1] - rs;
    const int tot = deg + 1;

    float4 ad4 = *(const float4*)&g_adst[n * HEADS];
    float ad[4] = {ad4.x, ad4.y, ad4.z, ad4.w};
    const int myh = lane >> 3;

    float acc[8] = {0.f, 0.f, 0.f, 0.f, 0.f, 0.f, 0.f, 0.f};

    if (tot <= CAP) {
        float m[4] = {-CUDART_INF_F, -CUDART_INF_F, -CUDART_INF_F, -CUDART_INF_F};
        for (int i = lane; i < tot; i += 32) {
            int src = (i < deg) ? g_csr[rs + i] : n;
            s_src[w][i] = src;
            float4 a4 = *(const float4*)&g_asrc[src * HEADS];
            float lg[4] = {a4.x + ad[0], a4.y + ad[1], a4.z + ad[2], a4.w + ad[3]};
            #pragma unroll
            for (int h = 0; h < 4; h++) {
                lg[h] = lg[h] >= 0.f ? lg[h] : NEG_SLOPE * lg[h];
                m[h] = fmaxf(m[h], lg[h]);
            }
            *(float4*)&s_lg[w][i][0] = make_float4(lg[0], lg[1], lg[2], lg[3]);
        }
        #pragma unroll
        for (int off = 16; off; off >>= 1)
            #pragma unroll
            for (int h = 0; h < 4; h++)
                m[h] = fmaxf(m[h], __shfl_xor_sync(0xffffffffu, m[h], off));

        float s[4] = {0.f, 0.f, 0.f, 0.f};
        for (int i = lane; i < tot; i += 32) {
            float4 L = *(const float4*)&s_lg[w][i][0];
            float e0 = __expf(L.x - m[0]);
            float e1 = __expf(L.y - m[1]);
            float e2 = __expf(L.z - m[2]);
            float e3 = __expf(L.w - m[3]);
            s[0] += e0; s[1] += e1; s[2] += e2; s[3] += e3;
            *(float4*)&s_lg[w][i][0] = make_float4(e0, e1, e2, e3);
        }
        #pragma unroll
        for (int off = 16; off; off >>= 1)
            #pragma unroll
            for (int h = 0; h < 4; h++)
                s[h] += __shfl_xor_sync(0xffffffffu, s[h], off);

        const float inv = 1.f / (s[myh] + 1e-16f);
        __syncwarp();

        int i = 0;
        for (; i + 4 <= tot; i += 4) {
            int   sA = s_src[w][i],     sB = s_src[w][i + 1];
            int   sC = s_src[w][i + 2], sD = s_src[w][i + 3];
            float aA = s_lg[w][i][myh] * inv,     aB = s_lg[w][i + 1][myh] * inv;
            float aC = s_lg[w][i + 2][myh] * inv, aD = s_lg[w][i + 3][myh] * inv;
            h8_accum(&g_hh[(size_t)sA * HC + lane * 8], aA, acc);
            h8_accum(&g_hh[(size_t)sB * HC + lane * 8], aB, acc);
            h8_accum(&g_hh[(size_t)sC * HC + lane * 8], aC, acc);
            h8_accum(&g_hh[(size_t)sD * HC + lane * 8], aD, acc);
        }
        for (; i < tot; i++) {
            int   s0 = s_src[w][i];
            float a0 = s_lg[w][i][myh] * inv;
            h8_accum(&g_hh[(size_t)s0 * HC + lane * 8], a0, acc);
        }
    } else {
        float m[4] = {-CUDART_INF_F, -CUDART_INF_F, -CUDART_INF_F, -CUDART_INF_F};
        for (int i = lane; i < tot; i += 32) {
            int src = (i < deg) ? g_csr[rs + i] : n;
            float4 a4 = *(const float4*)&g_asrc[src * HEADS];
            float lg[4] = {a4.x + ad[0], a4.y + ad[1], a4.z + ad[2], a4.w + ad[3]};
            #pragma unroll
            for (int h = 0; h < 4; h++) {
                float v = lg[h] >= 0.f ? lg[h] : NEG_SLOPE * lg[h];
                m[h] = fmaxf(m[h], v);
            }
        }
        #pragma unroll
        for (int off = 16; off; off >>= 1)
            #pragma unroll
            for (int h = 0; h < 4; h++)
                m[h] = fmaxf(m[h], __shfl_xor_sync(0xffffffffu, m[h], off));

        float s[4] = {0.f, 0.f, 0.f, 0.f};
        for (int i = lane; i < tot; i += 32) {
            int src = (i < deg) ? g_csr[rs + i] : n;
            float4 a4 = *(const float4*)&g_asrc[src * HEADS];
            float lg[4] = {a4.x + ad[0], a4.y + ad[1], a4.z + ad[2], a4.w + ad[3]};
            #pragma unroll
            for (int h = 0; h < 4; h++) {
                float v = lg[h] >= 0.f ? lg[h] : NEG_SLOPE * lg[h];
                s[h] += __expf(v - m[h]);
            }
        }
        #pragma unroll
        for (int off = 16; off; off >>= 1)
            #pragma unroll
            for (int h = 0; h < 4; h++)
                s[h] += __shfl_xor_sync(0xffffffffu, s[h], off);

        const float mh  = m[myh];
        const float inv = 1.f / (s[myh] + 1e-16f);
        const float adh = ad[myh];
        for (int i = 0; i < tot; i++) {
            int src = (i < deg) ? g_csr[rs + i] : n;
            float av = g_asrc[src * HEADS + myh];
            float lg = av + adh;
            lg = lg >= 0.f ? lg : NEG_SLOPE * lg;
            float alpha = __expf(lg - mh) * inv;
            h8_accum(&g_hh[(size_t)src * HC + lane * 8], alpha, acc);
        }
    }

    float4 b0 = ((const float4*)bias)[lane * 2];
    float4 b1 = ((const float4*)bias)[lane * 2 + 1];
    float4 o0, o1;
    o0.x = fmaxf(acc[0] + b0.x, 0.f); o0.y = fmaxf(acc[1] + b0.y, 0.f);
    o0.z = fmaxf(acc[2] + b0.z, 0.f); o0.w = fmaxf(acc[3] + b0.w, 0.f);
    o1.x = fmaxf(acc[4] + b1.x, 0.f); o1.y = fmaxf(acc[5] + b1.y, 0.f);
    o1.z = fmaxf(acc[6] + b1.z, 0.f); o1.w = fmaxf(acc[7] + b1.w, 0.f);
    *(float4*)&out[(size_t)n * HC + lane * 8]     = o0;
    *(float4*)&out[(size_t)n * HC + lane * 8 + 4] = o1;
}

// ---------------- launch ----------------
extern "C" void kernel_launch(void* const* d_in, const int* in_sizes, int n_in,
                              void* d_out, int out_size) {
    const float* x       = (const float*)d_in[0];
    const void*  ei      = d_in[1];
    const float* W       = (const float*)d_in[2];
    const float* att_src = (const float*)d_in[3];
    const float* att_dst = (const float*)d_in[4];
    const float* bias    = (const float*)d_in[5];
    float*       out     = (float*)d_out;

    cudaFuncSetAttribute(hgemm_kernel,
                         cudaFuncAttributeMaxDynamicSharedMemorySize, GEMM_SMEM);

    // fork
    cudaEventRecord(g_si.e1, 0);
    cudaStreamWaitEvent(g_si.s2, g_si.e1, 0);

    // side stream: W transpose first (GEMM waits on e3), then CSR build chain
    dim3 tg(8, 8);
    transpose_w_kernel<<<tg, dim3(32, 8), 0, g_si.s2>>>(W);
    cudaEventRecord(g_si.e3, g_si.s2);
    detect_kernel<<<1, 256, 0, g_si.s2>>>((const unsigned int*)ei);
    zero_deg_kernel<<<(N_NODES + 255) / 256, 256, 0, g_si.s2>>>();
    convert_kernel<<<(E_EDGES + 255) / 256, 256, 0, g_si.s2>>>(ei);
    scan_reduce_kernel<<<NSCAN, SCAN_BLK, 0, g_si.s2>>>();
    scan_offsets_kernel<<<1, 64, 0, g_si.s2>>>();
    scan_local_kernel<<<NSCAN, SCAN_BLK, 0, g_si.s2>>>();
    fill_kernel<<<(E_EDGES + 255) / 256, 256, 0, g_si.s2>>>();
    cudaEventRecord(g_si.e2, g_si.s2);

    // main stream: x->fp16, then GEMM (waits on transpose)
    convert_x_kernel<<<(N_NODES * IN_DIM / 8 + 255) / 256, 256>>>(x);
    cudaStreamWaitEvent(0, g_si.e3, 0);
    dim3 gg(HC / GBN, (N_NODES + GBM - 1) / GBM);   // (2, 391)
    hgemm_kernel<<<gg, 256, GEMM_SMEM>>>(att_src, att_dst);

    // join: gather needs both chains
    cudaStreamWaitEvent(0, g_si.e2, 0);
    gat_node_kernel<<<(N_NODES + 7) / 8, 256>>>(bias, out);
}